// round 1
// baseline (speedup 1.0000x reference)
#include <cuda_runtime.h>
#include <math.h>

// ---------------------------------------------------------------------------
// TensorizedSpectralConv: B=32, H=W=128, C_in=C_out=128, modes 32x17, deg 2, rank 64
//
// Pipeline (all unnormalized transforms; 1/(H*W) folded into K):
//   s_kernel    : S0[h,i,j,d] = sum_r ko0[h,i,d,r]*ki0[h,j,d,r]   (and S1 for w)
//   k_kernel    : K[h,w,i,j]  = (sum_d S0*S1) / 16384
//   fwdW_kernel : X1[b,w,y,c] = sum_x X[b,y,x,c] e^{-2pi i w x/128}, w<17
//   fwdH_kernel : Xf[h,w,b,c] = sum_y X1[b,w,y,c] e^{-2pi i m(h) y/128}
//   mix_kernel  : Yf[h,w,b,i] = sum_j K[h,w,i,j] Xf[h,w,b,j]
//   invH_kernel : Z[b,y,w,i]  = sum_h Yf[h,w,b,i] e^{+2pi i m(h) y/128}
//   invW_kernel : out[b,y,x,i]= Re(Z0) + 2*sum_{w=1..16} (Zr cos - Zi sin)
// m(h) = h for h<16 else 96+h  (rows 112..127)
// ---------------------------------------------------------------------------

#define BATCH 32
#define NHH   128
#define NWW   128
#define CI    128
#define CO    128
#define WM    17
#define HM    32
#define DEG   2
#define RANK  64
#define NHW   (HM*WM)   // 544

__device__ float2 g_S0[HM*CO*CI*DEG];        // 16.8 MB
__device__ float2 g_S1[WM*CO*CI*DEG];        //  8.9 MB
__device__ float2 g_K [NHW*CO*CI];           // 71.3 MB  [h][w][i][j]
__device__ float2 g_X1[BATCH*WM*NHH*CI];     // 71.3 MB  [b][w][y][c]
__device__ float2 g_Xf[NHW*BATCH*CI];        // 17.8 MB  [h][w][b][c]
__device__ float2 g_Yf[NHW*BATCH*CO];        // 17.8 MB  [h][w][b][i]
__device__ float2 g_Z [BATCH*NHH*WM*CO];     // 71.3 MB  [b][y][w][i]

__device__ __forceinline__ float2 cfma(float2 a, float2 b, float2 acc) {
    acc.x = fmaf(a.x, b.x, acc.x);
    acc.x = fmaf(-a.y, b.y, acc.x);
    acc.y = fmaf(a.x, b.y, acc.y);
    acc.y = fmaf(a.y, b.x, acc.y);
    return acc;
}

// ---------------------------------------------------------------------------
// S build: one block per (mode, d, i-chunk-of-16); 256 threads.
// thread: j = tid&127, owns 8 i's.
// ---------------------------------------------------------------------------
__global__ void __launch_bounds__(256) s_kernel(const float2* __restrict__ ko,
                                                const float2* __restrict__ ki,
                                                int which) {
    float2* S = which ? g_S1 : g_S0;
    int h  = blockIdx.x >> 1;
    int d  = blockIdx.x & 1;
    int i0 = blockIdx.y * 16;
    __shared__ float2 kis[128][33];
    __shared__ float2 kos[16][33];
    int tid = threadIdx.x;
    int j = tid & 127, ih = tid >> 7;

    float2 acc[8];
#pragma unroll
    for (int ii = 0; ii < 8; ii++) acc[ii] = make_float2(0.f, 0.f);

    for (int r0 = 0; r0 < RANK; r0 += 32) {
        __syncthreads();
        for (int t = tid; t < 128 * 32; t += 256) {
            int jj = t >> 5, r = t & 31;
            kis[jj][r] = ki[((h * CI + jj) * DEG + d) * RANK + r0 + r];
        }
        for (int t = tid; t < 16 * 32; t += 256) {
            int ii = t >> 5, r = t & 31;
            kos[ii][r] = ko[((h * CO + i0 + ii) * DEG + d) * RANK + r0 + r];
        }
        __syncthreads();
        for (int r = 0; r < 32; r++) {
            float2 bj = kis[j][r];
#pragma unroll
            for (int ii = 0; ii < 8; ii++)
                acc[ii] = cfma(kos[ih * 8 + ii][r], bj, acc[ii]);
        }
    }
#pragma unroll
    for (int ii = 0; ii < 8; ii++) {
        int i = i0 + ih * 8 + ii;
        S[((h * CO + i) * CI + j) * DEG + d] = acc[ii];
    }
}

// ---------------------------------------------------------------------------
// K combine: elementwise over (h,w,i,j). 1/16384 norm folded in.
// ---------------------------------------------------------------------------
__global__ void __launch_bounds__(256) k_kernel() {
    int hw = blockIdx.x;
    int h = hw / WM, w = hw % WM;
    int e = blockIdx.y * 256 + threadIdx.x;   // i*128 + j
    const float SCALE = 1.0f / 16384.0f;
    float2 a0 = g_S0[((size_t)h * CO * CI + e) * DEG + 0];
    float2 a1 = g_S0[((size_t)h * CO * CI + e) * DEG + 1];
    float2 b0 = g_S1[((size_t)w * CO * CI + e) * DEG + 0];
    float2 b1 = g_S1[((size_t)w * CO * CI + e) * DEG + 1];
    float2 k;
    k.x = a0.x * b0.x - a0.y * b0.y + a1.x * b1.x - a1.y * b1.y;
    k.y = a0.x * b0.y + a0.y * b0.x + a1.x * b1.y + a1.y * b1.x;
    g_K[(size_t)hw * CO * CI + e] = make_float2(k.x * SCALE, k.y * SCALE);
}

// ---------------------------------------------------------------------------
// Forward W DFT (real input, 17 modes). Block per (b,y); 128 threads = c.
// ---------------------------------------------------------------------------
__global__ void __launch_bounds__(128) fwdW_kernel(const float* __restrict__ X) {
    __shared__ float  xs[64 * 128];
    __shared__ float2 tw[128];   // e^{-2pi i k/128}
    int tid = threadIdx.x;
    {
        float s, c;
        sincospif((float)tid / 64.0f, &s, &c);
        tw[tid] = make_float2(c, -s);
    }
    int b = blockIdx.x >> 7, y = blockIdx.x & 127;
    const float* Xrow = X + (size_t)(b * NHH + y) * NWW * CI;

    float2 acc[WM];
#pragma unroll
    for (int w = 0; w < WM; w++) acc[w] = make_float2(0.f, 0.f);

    for (int xc = 0; xc < NWW; xc += 64) {
        __syncthreads();
        for (int t = tid; t < 64 * 128; t += 128) xs[t] = Xrow[xc * CI + t];
        __syncthreads();
        for (int xi = 0; xi < 64; xi++) {
            float v = xs[xi * 128 + tid];
            int x = xc + xi;
            int idx = 0;
#pragma unroll
            for (int w = 0; w < WM; w++) {
                float2 t = tw[idx];
                acc[w].x = fmaf(v, t.x, acc[w].x);
                acc[w].y = fmaf(v, t.y, acc[w].y);
                idx = (idx + x) & 127;
            }
        }
    }
    // X1[b][w][y][c]
    float2* dst = g_X1 + ((size_t)b * WM * NHH + y) * CI + tid;
#pragma unroll
    for (int w = 0; w < WM; w++) dst[(size_t)w * NHH * CI] = acc[w];
}

// ---------------------------------------------------------------------------
// Forward H DFT (32 kept modes). Block per (b,w); 1024 threads = 32 h x 32 cgrp.
// Thread: one h-mode, 4 consecutive channels.
// ---------------------------------------------------------------------------
__global__ void __launch_bounds__(1024) fwdH_kernel() {
    __shared__ float2 xs[16][132];
    __shared__ float2 tw[128];   // e^{-2pi i k/128}
    int tid = threadIdx.x;
    if (tid < 128) {
        float s, c;
        sincospif((float)tid / 64.0f, &s, &c);
        tw[tid] = make_float2(c, -s);
    }
    int b = blockIdx.x / WM, w = blockIdx.x % WM;
    int cg = tid & 31, h = tid >> 5;
    int c0 = cg * 4;
    int m = (h < 16) ? h : (96 + h);
    const float2* src = g_X1 + (size_t)(b * WM + w) * NHH * CI;

    float2 acc[4];
#pragma unroll
    for (int q = 0; q < 4; q++) acc[q] = make_float2(0.f, 0.f);

    for (int y0 = 0; y0 < NHH; y0 += 16) {
        __syncthreads();
        for (int t = tid; t < 16 * 128; t += 1024) {
            int yy = t >> 7, cc = t & 127;
            xs[yy][cc] = src[(size_t)(y0 + yy) * CI + cc];
        }
        __syncthreads();
        for (int yy = 0; yy < 16; yy++) {
            int idx = (m * (y0 + yy)) & 127;
            float2 t = tw[idx];
#pragma unroll
            for (int q = 0; q < 4; q++)
                acc[q] = cfma(t, xs[yy][c0 + q], acc[q]);
        }
    }
    // Xf[h][w][b][c]
    float2* dst = g_Xf + (size_t)((h * WM + w) * BATCH + b) * CI + c0;
#pragma unroll
    for (int q = 0; q < 4; q++) dst[q] = acc[q];
}

// ---------------------------------------------------------------------------
// Mode mix: per (h,w), Yf[b,i] = sum_j K[i,j] * Xf[b,j]. 512 threads,
// thread owns (i, 8 b's).
// ---------------------------------------------------------------------------
__global__ void __launch_bounds__(512) mix_kernel() {
    __shared__ float2 Ksm[16][130];
    __shared__ float2 xsm[32][17];
    int tid = threadIdx.x;
    int hw = blockIdx.x;
    int i = tid & 127, bq = tid >> 7;
    const float2* Kb = g_K  + (size_t)hw * CO * CI;
    const float2* Xb = g_Xf + (size_t)hw * BATCH * CI;

    float2 acc[8];
#pragma unroll
    for (int bb = 0; bb < 8; bb++) acc[bb] = make_float2(0.f, 0.f);

    for (int j0 = 0; j0 < CI; j0 += 16) {
        __syncthreads();
        for (int t = tid; t < 128 * 16; t += 512) {
            int ii = t >> 4, jj = t & 15;
            Ksm[jj][ii] = Kb[ii * CI + j0 + jj];
        }
        {
            int bb = tid >> 4, jj = tid & 15;
            xsm[bb][jj] = Xb[bb * CI + j0 + jj];
        }
        __syncthreads();
        for (int jj = 0; jj < 16; jj++) {
            float2 kv = Ksm[jj][i];
#pragma unroll
            for (int bb = 0; bb < 8; bb++)
                acc[bb] = cfma(kv, xsm[bq * 8 + bb][jj], acc[bb]);
        }
    }
    float2* dst = g_Yf + (size_t)hw * BATCH * CO;
#pragma unroll
    for (int bb = 0; bb < 8; bb++) dst[(bq * 8 + bb) * CO + i] = acc[bb];
}

// ---------------------------------------------------------------------------
// Inverse H: Z[b,y,w,i] = sum_h Yf[h,w,b,i] e^{+2pi i m(h) y/128}.
// Grid (b*17+w, yquarter); 512 threads: thread owns (i, 8 y's).
// ---------------------------------------------------------------------------
__global__ void __launch_bounds__(512) invH_kernel() {
    __shared__ float2 ys[32][129];
    __shared__ float2 tw[128];   // e^{+2pi i k/128}
    int tid = threadIdx.x;
    if (tid < 128) {
        float s, c;
        sincospif((float)tid / 64.0f, &s, &c);
        tw[tid] = make_float2(c, s);
    }
    int hw = blockIdx.x;
    int b = hw / WM, w = hw % WM;
    int y0 = blockIdx.y * 32;
    int i = tid & 127, ysub = tid >> 7;

    for (int t = tid; t < 32 * 128; t += 512) {
        int h = t >> 7, ii = t & 127;
        ys[h][ii] = g_Yf[(size_t)((h * WM + w) * BATCH + b) * CO + ii];
    }
    __syncthreads();

    float2 acc[8];
#pragma unroll
    for (int k = 0; k < 8; k++) acc[k] = make_float2(0.f, 0.f);

    for (int h = 0; h < HM; h++) {
        float2 v = ys[h][i];
        int m = (h < 16) ? h : (96 + h);
        int idx = (m * (y0 + ysub * 8)) & 127;
#pragma unroll
        for (int k = 0; k < 8; k++) {
            acc[k] = cfma(tw[idx], v, acc[k]);
            idx = (idx + m) & 127;
        }
    }
#pragma unroll
    for (int k = 0; k < 8; k++) {
        int y = y0 + ysub * 8 + k;
        g_Z[(size_t)((b * NHH + y) * WM + w) * CO + i] = acc[k];
    }
}

// ---------------------------------------------------------------------------
// Inverse W (hermitian, real output). Block per (b,y); 128 threads = i.
// Z row (17 complex per thread) lives in registers; only twiddle hits smem.
// ---------------------------------------------------------------------------
__global__ void __launch_bounds__(128) invW_kernel(float* __restrict__ out) {
    __shared__ float2 tw[128];   // e^{+2pi i k/128}
    int tid = threadIdx.x;
    {
        float s, c;
        sincospif((float)tid / 64.0f, &s, &c);
        tw[tid] = make_float2(c, s);
    }
    int b = blockIdx.x >> 7, y = blockIdx.x & 127;
    const float2* zrow = g_Z + (size_t)(b * NHH + y) * WM * CO;

    float zr[WM], zi[WM];
#pragma unroll
    for (int w = 0; w < WM; w++) {
        float2 v = zrow[w * CO + tid];
        float cw = (w == 0) ? 1.0f : 2.0f;
        zr[w] = v.x * cw;
        zi[w] = v.y * cw;
    }
    __syncthreads();

    float* orow = out + (size_t)(b * NHH + y) * NWW * CO;
    for (int x = 0; x < NWW; x++) {
        float acc = zr[0];          // imag(DC) dropped, matching C2R semantics
        int idx = 0;
#pragma unroll
        for (int w = 1; w < WM; w++) {
            idx = (idx + x) & 127;
            float2 t = tw[idx];
            acc = fmaf(zr[w], t.x, acc);
            acc = fmaf(-zi[w], t.y, acc);
        }
        orow[x * CO + tid] = acc;
    }
}

// ---------------------------------------------------------------------------
extern "C" void kernel_launch(void* const* d_in, const int* in_sizes, int n_in,
                              void* d_out, int out_size) {
    const float*  X   = (const float*) d_in[0];
    const float2* ko0 = (const float2*)d_in[1];
    const float2* ki0 = (const float2*)d_in[2];
    const float2* ko1 = (const float2*)d_in[3];
    const float2* ki1 = (const float2*)d_in[4];
    float* out = (float*)d_out;

    s_kernel<<<dim3(HM * DEG, 8), 256>>>(ko0, ki0, 0);
    s_kernel<<<dim3(WM * DEG, 8), 256>>>(ko1, ki1, 1);
    k_kernel<<<dim3(NHW, 64), 256>>>();
    fwdW_kernel<<<BATCH * NHH, 128>>>(X);
    fwdH_kernel<<<BATCH * WM, 1024>>>();
    mix_kernel<<<NHW, 512>>>();
    invH_kernel<<<dim3(BATCH * WM, 4), 512>>>();
    invW_kernel<<<BATCH * NHH, 128>>>(out);
}

// round 2
// speedup vs baseline: 1.0048x; 1.0048x over previous
#include <cuda_runtime.h>
#include <math.h>

// ---------------------------------------------------------------------------
// TensorizedSpectralConv: B=32, H=W=128, C_in=C_out=128, modes 32x17, deg 2, rank 64
//
// Pipeline (all unnormalized transforms; 1/(H*W) folded into K):
//   s_kernel    : S0[h,i,j,d] = sum_r ko0[h,i,d,r]*ki0[h,j,d,r]   (and S1 for w)
//   k_kernel    : K[h,w,i,j]  = (sum_d S0*S1) / 16384
//   fwdW_kernel : X1[b,w,y,c] = sum_x X[b,y,x,c] e^{-2pi i w x/128}, w<17
//   fwdH_kernel : Xf[h,w,b,c] = sum_y X1[b,w,y,c] e^{-2pi i m(h) y/128}
//   mix_kernel  : Yf[h,w,b,i] = sum_j K[h,w,i,j] Xf[h,w,b,j]
//   invH_kernel : Z[b,y,w,i]  = sum_h Yf[h,w,b,i] e^{+2pi i m(h) y/128}
//   invW_kernel : out[b,y,x,i]= Re(Z0) + 2*sum_{w=1..16} (Zr cos - Zi sin)
// m(h) = h for h<16 else 96+h  (rows 112..127)
// ---------------------------------------------------------------------------

#define BATCH 32
#define NHH   128
#define NWW   128
#define CI    128
#define CO    128
#define WM    17
#define HM    32
#define DEG   2
#define RANK  64
#define NHW   (HM*WM)   // 544

__device__ float2 g_S0[HM*CO*CI*DEG];        // 16.8 MB
__device__ float2 g_S1[WM*CO*CI*DEG];        //  8.9 MB
__device__ float2 g_K [NHW*CO*CI];           // 71.3 MB  [h][w][i][j]
__device__ float2 g_X1[BATCH*WM*NHH*CI];     // 71.3 MB  [b][w][y][c]
__device__ float2 g_Xf[NHW*BATCH*CI];        // 17.8 MB  [h][w][b][c]
__device__ float2 g_Yf[NHW*BATCH*CO];        // 17.8 MB  [h][w][b][i]
__device__ float2 g_Z [BATCH*NHH*WM*CO];     // 71.3 MB  [b][y][w][i]

__device__ __forceinline__ float2 cfma(float2 a, float2 b, float2 acc) {
    acc.x = fmaf(a.x, b.x, acc.x);
    acc.x = fmaf(-a.y, b.y, acc.x);
    acc.y = fmaf(a.x, b.y, acc.y);
    acc.y = fmaf(a.y, b.x, acc.y);
    return acc;
}

// ---------------------------------------------------------------------------
// S build: one block per (mode, d, i-chunk-of-16); 256 threads.
// thread: j = tid&127, owns 8 i's.
// ---------------------------------------------------------------------------
__global__ void __launch_bounds__(256) s_kernel(const float2* __restrict__ ko,
                                                const float2* __restrict__ ki,
                                                int which) {
    float2* S = which ? g_S1 : g_S0;
    int h  = blockIdx.x >> 1;
    int d  = blockIdx.x & 1;
    int i0 = blockIdx.y * 16;
    __shared__ float2 kis[128][33];
    __shared__ float2 kos[16][33];
    int tid = threadIdx.x;
    int j = tid & 127, ih = tid >> 7;

    float2 acc[8];
#pragma unroll
    for (int ii = 0; ii < 8; ii++) acc[ii] = make_float2(0.f, 0.f);

    for (int r0 = 0; r0 < RANK; r0 += 32) {
        __syncthreads();
        for (int t = tid; t < 128 * 32; t += 256) {
            int jj = t >> 5, r = t & 31;
            kis[jj][r] = ki[((h * CI + jj) * DEG + d) * RANK + r0 + r];
        }
        for (int t = tid; t < 16 * 32; t += 256) {
            int ii = t >> 5, r = t & 31;
            kos[ii][r] = ko[((h * CO + i0 + ii) * DEG + d) * RANK + r0 + r];
        }
        __syncthreads();
        for (int r = 0; r < 32; r++) {
            float2 bj = kis[j][r];
#pragma unroll
            for (int ii = 0; ii < 8; ii++)
                acc[ii] = cfma(kos[ih * 8 + ii][r], bj, acc[ii]);
        }
    }
#pragma unroll
    for (int ii = 0; ii < 8; ii++) {
        int i = i0 + ih * 8 + ii;
        S[((h * CO + i) * CI + j) * DEG + d] = acc[ii];
    }
}

// ---------------------------------------------------------------------------
// K combine: elementwise over (h,w,i,j). 1/16384 norm folded in.
// ---------------------------------------------------------------------------
__global__ void __launch_bounds__(256) k_kernel() {
    int hw = blockIdx.x;
    int h = hw / WM, w = hw % WM;
    int e = blockIdx.y * 256 + threadIdx.x;   // i*128 + j
    const float SCALE = 1.0f / 16384.0f;
    float2 a0 = g_S0[((size_t)h * CO * CI + e) * DEG + 0];
    float2 a1 = g_S0[((size_t)h * CO * CI + e) * DEG + 1];
    float2 b0 = g_S1[((size_t)w * CO * CI + e) * DEG + 0];
    float2 b1 = g_S1[((size_t)w * CO * CI + e) * DEG + 1];
    float2 k;
    k.x = a0.x * b0.x - a0.y * b0.y + a1.x * b1.x - a1.y * b1.y;
    k.y = a0.x * b0.y + a0.y * b0.x + a1.x * b1.y + a1.y * b1.x;
    g_K[(size_t)hw * CO * CI + e] = make_float2(k.x * SCALE, k.y * SCALE);
}

// ---------------------------------------------------------------------------
// Forward W DFT (real input, 17 modes). Block per (b,y); 128 threads = c.
// ---------------------------------------------------------------------------
__global__ void __launch_bounds__(128) fwdW_kernel(const float* __restrict__ X) {
    __shared__ float  xs[64 * 128];
    __shared__ float2 tw[128];   // e^{-2pi i k/128}
    int tid = threadIdx.x;
    {
        float s, c;
        sincospif((float)tid / 64.0f, &s, &c);
        tw[tid] = make_float2(c, -s);
    }
    int b = blockIdx.x >> 7, y = blockIdx.x & 127;
    const float* Xrow = X + (size_t)(b * NHH + y) * NWW * CI;

    float2 acc[WM];
#pragma unroll
    for (int w = 0; w < WM; w++) acc[w] = make_float2(0.f, 0.f);

    for (int xc = 0; xc < NWW; xc += 64) {
        __syncthreads();
        for (int t = tid; t < 64 * 128; t += 128) xs[t] = Xrow[xc * CI + t];
        __syncthreads();
        for (int xi = 0; xi < 64; xi++) {
            float v = xs[xi * 128 + tid];
            int x = xc + xi;
            int idx = 0;
#pragma unroll
            for (int w = 0; w < WM; w++) {
                float2 t = tw[idx];
                acc[w].x = fmaf(v, t.x, acc[w].x);
                acc[w].y = fmaf(v, t.y, acc[w].y);
                idx = (idx + x) & 127;
            }
        }
    }
    // X1[b][w][y][c]
    float2* dst = g_X1 + ((size_t)b * WM * NHH + y) * CI + tid;
#pragma unroll
    for (int w = 0; w < WM; w++) dst[(size_t)w * NHH * CI] = acc[w];
}

// ---------------------------------------------------------------------------
// Forward H DFT (32 kept modes). Block per (b,w); 1024 threads = 32 h x 32 cgrp.
// Thread: one h-mode, 4 consecutive channels.
// ---------------------------------------------------------------------------
__global__ void __launch_bounds__(1024) fwdH_kernel() {
    __shared__ float2 xs[16][132];
    __shared__ float2 tw[128];   // e^{-2pi i k/128}
    int tid = threadIdx.x;
    if (tid < 128) {
        float s, c;
        sincospif((float)tid / 64.0f, &s, &c);
        tw[tid] = make_float2(c, -s);
    }
    int b = blockIdx.x / WM, w = blockIdx.x % WM;
    int cg = tid & 31, h = tid >> 5;
    int c0 = cg * 4;
    int m = (h < 16) ? h : (96 + h);
    const float2* src = g_X1 + (size_t)(b * WM + w) * NHH * CI;

    float2 acc[4];
#pragma unroll
    for (int q = 0; q < 4; q++) acc[q] = make_float2(0.f, 0.f);

    for (int y0 = 0; y0 < NHH; y0 += 16) {
        __syncthreads();
        for (int t = tid; t < 16 * 128; t += 1024) {
            int yy = t >> 7, cc = t & 127;
            xs[yy][cc] = src[(size_t)(y0 + yy) * CI + cc];
        }
        __syncthreads();
        for (int yy = 0; yy < 16; yy++) {
            int idx = (m * (y0 + yy)) & 127;
            float2 t = tw[idx];
#pragma unroll
            for (int q = 0; q < 4; q++)
                acc[q] = cfma(t, xs[yy][c0 + q], acc[q]);
        }
    }
    // Xf[h][w][b][c]
    float2* dst = g_Xf + (size_t)((h * WM + w) * BATCH + b) * CI + c0;
#pragma unroll
    for (int q = 0; q < 4; q++) dst[q] = acc[q];
}

// ---------------------------------------------------------------------------
// Mode mix: per (h,w), Yf[b,i] = sum_j K[i,j] * Xf[b,j]. 512 threads,
// thread owns (i, 8 b's).
// ---------------------------------------------------------------------------
__global__ void __launch_bounds__(512) mix_kernel() {
    __shared__ float2 Ksm[16][130];
    __shared__ float2 xsm[32][17];
    int tid = threadIdx.x;
    int hw = blockIdx.x;
    int i = tid & 127, bq = tid >> 7;
    const float2* Kb = g_K  + (size_t)hw * CO * CI;
    const float2* Xb = g_Xf + (size_t)hw * BATCH * CI;

    float2 acc[8];
#pragma unroll
    for (int bb = 0; bb < 8; bb++) acc[bb] = make_float2(0.f, 0.f);

    for (int j0 = 0; j0 < CI; j0 += 16) {
        __syncthreads();
        for (int t = tid; t < 128 * 16; t += 512) {
            int ii = t >> 4, jj = t & 15;
            Ksm[jj][ii] = Kb[ii * CI + j0 + jj];
        }
        {
            int bb = tid >> 4, jj = tid & 15;
            xsm[bb][jj] = Xb[bb * CI + j0 + jj];
        }
        __syncthreads();
        for (int jj = 0; jj < 16; jj++) {
            float2 kv = Ksm[jj][i];
#pragma unroll
            for (int bb = 0; bb < 8; bb++)
                acc[bb] = cfma(kv, xsm[bq * 8 + bb][jj], acc[bb]);
        }
    }
    float2* dst = g_Yf + (size_t)hw * BATCH * CO;
#pragma unroll
    for (int bb = 0; bb < 8; bb++) dst[(bq * 8 + bb) * CO + i] = acc[bb];
}

// ---------------------------------------------------------------------------
// Inverse H: Z[b,y,w,i] = sum_h Yf[h,w,b,i] e^{+2pi i m(h) y/128}.
// Grid (b*17+w, yquarter); 512 threads: thread owns (i, 8 y's).
// ---------------------------------------------------------------------------
__global__ void __launch_bounds__(512) invH_kernel() {
    __shared__ float2 ys[32][129];
    __shared__ float2 tw[128];   // e^{+2pi i k/128}
    int tid = threadIdx.x;
    if (tid < 128) {
        float s, c;
        sincospif((float)tid / 64.0f, &s, &c);
        tw[tid] = make_float2(c, s);
    }
    int hw = blockIdx.x;
    int b = hw / WM, w = hw % WM;
    int y0 = blockIdx.y * 32;
    int i = tid & 127, ysub = tid >> 7;

    for (int t = tid; t < 32 * 128; t += 512) {
        int h = t >> 7, ii = t & 127;
        ys[h][ii] = g_Yf[(size_t)((h * WM + w) * BATCH + b) * CO + ii];
    }
    __syncthreads();

    float2 acc[8];
#pragma unroll
    for (int k = 0; k < 8; k++) acc[k] = make_float2(0.f, 0.f);

    for (int h = 0; h < HM; h++) {
        float2 v = ys[h][i];
        int m = (h < 16) ? h : (96 + h);
        int idx = (m * (y0 + ysub * 8)) & 127;
#pragma unroll
        for (int k = 0; k < 8; k++) {
            acc[k] = cfma(tw[idx], v, acc[k]);
            idx = (idx + m) & 127;
        }
    }
#pragma unroll
    for (int k = 0; k < 8; k++) {
        int y = y0 + ysub * 8 + k;
        g_Z[(size_t)((b * NHH + y) * WM + w) * CO + i] = acc[k];
    }
}

// ---------------------------------------------------------------------------
// Inverse W (hermitian, real output). Block per (b,y); 128 threads = i.
// Z row (17 complex per thread) lives in registers; only twiddle hits smem.
// ---------------------------------------------------------------------------
__global__ void __launch_bounds__(128) invW_kernel(float* __restrict__ out) {
    __shared__ float2 tw[128];   // e^{+2pi i k/128}
    int tid = threadIdx.x;
    {
        float s, c;
        sincospif((float)tid / 64.0f, &s, &c);
        tw[tid] = make_float2(c, s);
    }
    int b = blockIdx.x >> 7, y = blockIdx.x & 127;
    const float2* zrow = g_Z + (size_t)(b * NHH + y) * WM * CO;

    float zr[WM], zi[WM];
#pragma unroll
    for (int w = 0; w < WM; w++) {
        float2 v = zrow[w * CO + tid];
        float cw = (w == 0) ? 1.0f : 2.0f;
        zr[w] = v.x * cw;
        zi[w] = v.y * cw;
    }
    __syncthreads();

    float* orow = out + (size_t)(b * NHH + y) * NWW * CO;
    for (int x = 0; x < NWW; x++) {
        float acc = zr[0];          // imag(DC) dropped, matching C2R semantics
        int idx = 0;
#pragma unroll
        for (int w = 1; w < WM; w++) {
            idx = (idx + x) & 127;
            float2 t = tw[idx];
            acc = fmaf(zr[w], t.x, acc);
            acc = fmaf(-zi[w], t.y, acc);
        }
        orow[x * CO + tid] = acc;
    }
}

// ---------------------------------------------------------------------------
extern "C" void kernel_launch(void* const* d_in, const int* in_sizes, int n_in,
                              void* d_out, int out_size) {
    const float*  X   = (const float*) d_in[0];
    const float2* ko0 = (const float2*)d_in[1];
    const float2* ki0 = (const float2*)d_in[2];
    const float2* ko1 = (const float2*)d_in[3];
    const float2* ki1 = (const float2*)d_in[4];
    float* out = (float*)d_out;

    s_kernel<<<dim3(HM * DEG, 8), 256>>>(ko0, ki0, 0);
    s_kernel<<<dim3(WM * DEG, 8), 256>>>(ko1, ki1, 1);
    k_kernel<<<dim3(NHW, 64), 256>>>();
    fwdW_kernel<<<BATCH * NHH, 128>>>(X);
    fwdH_kernel<<<BATCH * WM, 1024>>>();
    mix_kernel<<<NHW, 512>>>();
    invH_kernel<<<dim3(BATCH * WM, 4), 512>>>();
    invW_kernel<<<BATCH * NHH, 128>>>(out);
}

// round 3
// speedup vs baseline: 1.7874x; 1.7789x over previous
#include <cuda_runtime.h>
#include <math.h>

// ---------------------------------------------------------------------------
// TensorizedSpectralConv: B=32, H=W=128, C=128, modes 32x17, deg 2, rank 64
// Round 2: conjugate-pair symmetry + fma.rn.f32x2 packing in all DFT stages.
// ---------------------------------------------------------------------------

#define BATCH 32
#define NHH   128
#define NWW   128
#define CI    128
#define CO    128
#define WM    17
#define HM    32
#define DEG   2
#define RANK  64
#define NHW   (HM*WM)   // 544

typedef unsigned long long u64;

__device__ float  g_X1re[BATCH*WM*NHH*CI];   // 35.6 MB  [b][w][y][c]
__device__ float  g_X1im[BATCH*WM*NHH*CI];   // 35.6 MB
__device__ float2 g_S0[HM*CO*CI*DEG];        // 16.8 MB
__device__ float2 g_S1[WM*CO*CI*DEG];        //  8.9 MB
__device__ float2 g_K [NHW*CO*CI];           // 71.3 MB  [h][w][i][j]
__device__ float2 g_Xf[NHW*BATCH*CI];        // 17.8 MB  [h][w][b][c]
__device__ float2 g_Yf[NHW*BATCH*CO];        // 17.8 MB  [h][w][b][i]
__device__ float2 g_Z [BATCH*NHH*WM*CO];     // 71.3 MB  [b][y][w][i]

__device__ __forceinline__ u64 pk2(float x, float y) {
    u64 r; asm("mov.b64 %0,{%1,%2};" : "=l"(r) : "f"(x), "f"(y)); return r;
}
__device__ __forceinline__ void up2(u64 v, float& x, float& y) {
    asm("mov.b64 {%0,%1},%2;" : "=f"(x), "=f"(y) : "l"(v));
}
__device__ __forceinline__ u64 f2fma(u64 a, u64 b, u64 c) {
    u64 d; asm("fma.rn.f32x2 %0,%1,%2,%3;" : "=l"(d) : "l"(a), "l"(b), "l"(c)); return d;
}
__device__ __forceinline__ u64 f2add(u64 a, u64 b) {
    u64 d; asm("add.rn.f32x2 %0,%1,%2;" : "=l"(d) : "l"(a), "l"(b)); return d;
}

__device__ __forceinline__ float2 cfma(float2 a, float2 b, float2 acc) {
    acc.x = fmaf(a.x, b.x, acc.x);
    acc.x = fmaf(-a.y, b.y, acc.x);
    acc.y = fmaf(a.x, b.y, acc.y);
    acc.y = fmaf(a.y, b.x, acc.y);
    return acc;
}

// ---------------------------------------------------------------------------
// S build: one block per (mode, d, i-chunk-of-16); 256 threads.
// ---------------------------------------------------------------------------
__global__ void __launch_bounds__(256) s_kernel(const float2* __restrict__ ko,
                                                const float2* __restrict__ ki,
                                                int which) {
    float2* S = which ? g_S1 : g_S0;
    int h  = blockIdx.x >> 1;
    int d  = blockIdx.x & 1;
    int i0 = blockIdx.y * 16;
    __shared__ float2 kis[128][33];
    __shared__ float2 kos[16][33];
    int tid = threadIdx.x;
    int j = tid & 127, ih = tid >> 7;

    float2 acc[8];
#pragma unroll
    for (int ii = 0; ii < 8; ii++) acc[ii] = make_float2(0.f, 0.f);

    for (int r0 = 0; r0 < RANK; r0 += 32) {
        __syncthreads();
        for (int t = tid; t < 128 * 32; t += 256) {
            int jj = t >> 5, r = t & 31;
            kis[jj][r] = ki[((h * CI + jj) * DEG + d) * RANK + r0 + r];
        }
        for (int t = tid; t < 16 * 32; t += 256) {
            int ii = t >> 5, r = t & 31;
            kos[ii][r] = ko[((h * CO + i0 + ii) * DEG + d) * RANK + r0 + r];
        }
        __syncthreads();
        for (int r = 0; r < 32; r++) {
            float2 bj = kis[j][r];
#pragma unroll
            for (int ii = 0; ii < 8; ii++)
                acc[ii] = cfma(kos[ih * 8 + ii][r], bj, acc[ii]);
        }
    }
#pragma unroll
    for (int ii = 0; ii < 8; ii++) {
        int i = i0 + ih * 8 + ii;
        S[((h * CO + i) * CI + j) * DEG + d] = acc[ii];
    }
}

// ---------------------------------------------------------------------------
// K combine, 1/16384 folded in.
// ---------------------------------------------------------------------------
__global__ void __launch_bounds__(256) k_kernel() {
    int hw = blockIdx.x;
    int h = hw / WM, w = hw % WM;
    int e = blockIdx.y * 256 + threadIdx.x;
    const float SCALE = 1.0f / 16384.0f;
    float2 a0 = g_S0[((size_t)h * CO * CI + e) * DEG + 0];
    float2 a1 = g_S0[((size_t)h * CO * CI + e) * DEG + 1];
    float2 b0 = g_S1[((size_t)w * CO * CI + e) * DEG + 0];
    float2 b1 = g_S1[((size_t)w * CO * CI + e) * DEG + 1];
    float2 k;
    k.x = a0.x * b0.x - a0.y * b0.y + a1.x * b1.x - a1.y * b1.y;
    k.y = a0.x * b0.y + a0.y * b0.x + a1.x * b1.y + a1.y * b1.x;
    g_K[(size_t)hw * CO * CI + e] = make_float2(k.x * SCALE, k.y * SCALE);
}

// ---------------------------------------------------------------------------
// Forward W DFT (real input, 17 modes), pair symmetry + f32x2.
// Block per (b,y); 128 threads = c.  acc[w] = (re, im).
// Pair (x, 128-x): s=v+v', d=v-v'; contrib = (s*cos, -d*sin).
// ---------------------------------------------------------------------------
__global__ void __launch_bounds__(128) fwdW_kernel(const float* __restrict__ X) {
    __shared__ u64 tw2[17][65];   // (cos(2pi w x/128), -sin(...)) for x in [0,64]
    int tid = threadIdx.x;
    for (int t = tid; t < 17 * 65; t += 128) {
        int w = t / 65, x = t % 65;
        float s, c;
        sincospif((float)(w * x) / 64.0f, &s, &c);
        tw2[w][x] = pk2(c, -s);
    }
    __syncthreads();

    int b = blockIdx.x >> 7, y = blockIdx.x & 127;
    const float* base = X + ((size_t)(b * NHH + y) * NWW) * CI + tid;

    float v0  = base[0];
    float v64 = base[64 * CI];
    u64 acc[WM];
#pragma unroll
    for (int w = 0; w < WM; w++)
        acc[w] = pk2(v0 + ((w & 1) ? -v64 : v64), 0.f);

    float va = base[1 * CI], vb = base[127 * CI];
    for (int x = 1; x < 63; x++) {
        float na = base[(x + 1) * CI];
        float nb = base[(127 - x) * CI];
        u64 sd = pk2(va + vb, va - vb);
#pragma unroll
        for (int w = 0; w < WM; w++)
            acc[w] = f2fma(sd, tw2[w][x], acc[w]);
        va = na; vb = nb;
    }
    {
        u64 sd = pk2(va + vb, va - vb);
#pragma unroll
        for (int w = 0; w < WM; w++)
            acc[w] = f2fma(sd, tw2[w][63], acc[w]);
    }

    size_t dst = ((size_t)b * WM * NHH + y) * CI + tid;
#pragma unroll
    for (int w = 0; w < WM; w++) {
        float re, im; up2(acc[w], re, im);
        g_X1re[dst + (size_t)w * NHH * CI] = re;
        g_X1im[dst + (size_t)w * NHH * CI] = im;
    }
}

// ---------------------------------------------------------------------------
// Forward H DFT (32 kept modes), pair symmetry over y + f32x2.
// Block per (b,w); 1024 threads = 32 h x 32 lanes; thread owns 4 channels
// c = lane + 32*q.  Staged smem: sn[yy][c]=(s.re,s.im), dm[yy][c]=(d.im,-d.re).
// contrib = s*cos(th) - i*d*sin(th), th = 2pi m y/128.
// ---------------------------------------------------------------------------
__global__ void __launch_bounds__(1024) fwdH_kernel() {
    __shared__ u64 sn[21][128];
    __shared__ u64 dm[21][128];
    __shared__ u64 twcc[128];   // (cos, cos)
    __shared__ u64 twss[128];   // (sin, sin)
    int tid = threadIdx.x;
    if (tid < 128) {
        float s, c;
        sincospif((float)tid / 64.0f, &s, &c);
        twcc[tid] = pk2(c, c);
        twss[tid] = pk2(s, s);
    }
    int b = blockIdx.x / WM, w = blockIdx.x % WM;
    int lane = tid & 31, h = tid >> 5;
    int m = (h < 16) ? h : (96 + h);
    size_t src = ((size_t)b * WM + w) * NHH * CI;
    const float* re_p = g_X1re + src;
    const float* im_p = g_X1im + src;

    // init with y=0 and y=64 contributions: acc = x0 + (-1)^m * x64
    float sgn = (h & 1) ? -1.f : 1.f;
    u64 acc[4];
#pragma unroll
    for (int q = 0; q < 4; q++) {
        int c = lane + 32 * q;
        float r0 = re_p[c],          i0 = im_p[c];
        float r6 = re_p[64 * CI + c], i6 = im_p[64 * CI + c];
        acc[q] = pk2(fmaf(sgn, r6, r0), fmaf(sgn, i6, i0));
    }

    for (int chunk = 0; chunk < 3; chunk++) {
        int ypb = 1 + chunk * 21;
        __syncthreads();
        for (int t = tid; t < 21 * 128; t += 1024) {
            int yy = t >> 7, cc = t & 127;
            int yp = ypb + yy;
            float ar = re_p[(size_t)yp * CI + cc];
            float br = re_p[(size_t)(128 - yp) * CI + cc];
            float ai = im_p[(size_t)yp * CI + cc];
            float bi = im_p[(size_t)(128 - yp) * CI + cc];
            sn[yy][cc] = pk2(ar + br, ai + bi);
            dm[yy][cc] = pk2(ai - bi, -(ar - br));
        }
        __syncthreads();
#pragma unroll 3
        for (int yy = 0; yy < 21; yy++) {
            int idx = (m * (ypb + yy)) & 127;
            u64 cc = twcc[idx], ss = twss[idx];
#pragma unroll
            for (int q = 0; q < 4; q++) {
                int c = lane + 32 * q;
                acc[q] = f2fma(sn[yy][c], cc, acc[q]);
                acc[q] = f2fma(dm[yy][c], ss, acc[q]);
            }
        }
    }
    // Xf[h][w][b][c]
    u64* dst = (u64*)g_Xf + ((size_t)(h * WM + w) * BATCH + b) * CI;
#pragma unroll
    for (int q = 0; q < 4; q++) dst[lane + 32 * q] = acc[q];
}

// ---------------------------------------------------------------------------
// Mode mix (unchanged scalar): per (h,w), Yf[b,i] = sum_j K[i,j] Xf[b,j].
// ---------------------------------------------------------------------------
__global__ void __launch_bounds__(512) mix_kernel() {
    __shared__ float2 Ksm[16][130];
    __shared__ float2 xsm[32][17];
    int tid = threadIdx.x;
    int hw = blockIdx.x;
    int i = tid & 127, bq = tid >> 7;
    const float2* Kb = g_K  + (size_t)hw * CO * CI;
    const float2* Xb = g_Xf + (size_t)hw * BATCH * CI;

    float2 acc[8];
#pragma unroll
    for (int bb = 0; bb < 8; bb++) acc[bb] = make_float2(0.f, 0.f);

    for (int j0 = 0; j0 < CI; j0 += 16) {
        __syncthreads();
        for (int t = tid; t < 128 * 16; t += 512) {
            int ii = t >> 4, jj = t & 15;
            Ksm[jj][ii] = Kb[ii * CI + j0 + jj];
        }
        {
            int bb = tid >> 4, jj = tid & 15;
            xsm[bb][jj] = Xb[bb * CI + j0 + jj];
        }
        __syncthreads();
        for (int jj = 0; jj < 16; jj++) {
            float2 kv = Ksm[jj][i];
#pragma unroll
            for (int bb = 0; bb < 8; bb++)
                acc[bb] = cfma(kv, xsm[bq * 8 + bb][jj], acc[bb]);
        }
    }
    float2* dst = g_Yf + (size_t)hw * BATCH * CO;
#pragma unroll
    for (int bb = 0; bb < 8; bb++) dst[(bq * 8 + bb) * CO + i] = acc[bb];
}

// ---------------------------------------------------------------------------
// Inverse H: Z[b,y,w,i] = sum_h Yf[h,w,b,i] e^{+2pi i m(h) y/128}.
// Mode-pair symmetry (m, -m) + f32x2. Grid (b*17+w, yq); 512 thr = (i, 4 ysub).
// pair contrib = s*cos(th) + i*d*sin(th); s=Y[m]+Y[-m], d=Y[m]-Y[-m].
// ---------------------------------------------------------------------------
__global__ void __launch_bounds__(512) invH_kernel() {
    __shared__ u64 ys[32][128];
    __shared__ u64 twcc[128];
    __shared__ u64 twss[128];
    int tid = threadIdx.x;
    if (tid < 128) {
        float s, c;
        sincospif((float)tid / 64.0f, &s, &c);
        twcc[tid] = pk2(c, c);
        twss[tid] = pk2(s, s);
    }
    int hw = blockIdx.x;
    int b = hw / WM, w = hw % WM;
    int y0 = blockIdx.y * 32;
    int i = tid & 127, ysub = tid >> 7;
    int yb = y0 + ysub * 8;

    const u64* Ysrc = (const u64*)g_Yf;
    for (int t = tid; t < 32 * 128; t += 512) {
        int h = t >> 7, ii = t & 127;
        ys[h][ii] = Ysrc[((size_t)(h * WM + w) * BATCH + b) * CO + ii];
    }
    __syncthreads();

    u64 acc[8];
    // m = 0 term
    {
        u64 v0 = ys[0][i];
#pragma unroll
        for (int k = 0; k < 8; k++) acc[k] = v0;
    }
    // m = -16 term (h=16): contrib = v * e^{-i*2pi*16*y/128}
    {
        u64 v = ys[16][i];
        float vr, vi; up2(v, vr, vi);
        u64 vs = pk2(vi, -vr);
        int idx = (16 * yb) & 127;
#pragma unroll
        for (int k = 0; k < 8; k++) {
            acc[k] = f2fma(v,  twcc[idx], acc[k]);
            acc[k] = f2fma(vs, twss[idx], acc[k]);
            idx = (idx + 16) & 127;
        }
    }
    // paired modes m=1..15 with h2 = 32-m
#pragma unroll 3
    for (int m = 1; m < 16; m++) {
        u64 y1 = ys[m][i];
        u64 y2 = ys[32 - m][i];
        float ar, ai, br, bi;
        up2(y1, ar, ai); up2(y2, br, bi);
        u64 s  = pk2(ar + br, ai + bi);
        u64 dp = pk2(-(ai - bi), ar - br);   // (-d.im, d.re)
        int idx = (m * yb) & 127;
#pragma unroll
        for (int k = 0; k < 8; k++) {
            acc[k] = f2fma(s,  twcc[idx], acc[k]);
            acc[k] = f2fma(dp, twss[idx], acc[k]);
            idx = (idx + m) & 127;
        }
    }
    u64* Zd = (u64*)g_Z;
#pragma unroll
    for (int k = 0; k < 8; k++) {
        int y = yb + k;
        Zd[((size_t)(b * NHH + y) * WM + w) * CO + i] = acc[k];
    }
}

// ---------------------------------------------------------------------------
// Inverse W (hermitian, real output), pair symmetry + f32x2.
// Block per (b,y); 128 threads = i.  acc=(a,bh): a=sum zr*cos, bh=-sum zi*sin.
// out[x]=a+bh, out[128-x]=a-bh.
// ---------------------------------------------------------------------------
__global__ void __launch_bounds__(128) invW_kernel(float* __restrict__ out) {
    __shared__ u64 tw2[17][65];   // (cos(2pi w x/128), -sin(...))
    int tid = threadIdx.x;
    for (int t = tid; t < 17 * 65; t += 128) {
        int w = t / 65, x = t % 65;
        float s, c;
        sincospif((float)(w * x) / 64.0f, &s, &c);
        tw2[w][x] = pk2(c, -s);
    }
    __syncthreads();

    int b = blockIdx.x >> 7, y = blockIdx.x & 127;
    const float2* zrow = g_Z + (size_t)(b * NHH + y) * WM * CO;

    u64 zw[WM];
#pragma unroll
    for (int w = 0; w < WM; w++) {
        float2 v = zrow[w * CO + tid];
        float cw = (w == 0) ? 1.0f : 2.0f;
        zw[w] = pk2(v.x * cw, v.y * cw);
    }

    float* orow = out + (size_t)(b * NHH + y) * NWW * CO + tid;
    for (int x = 0; x <= 64; x++) {
        u64 acc = zw[0];   // w=0: tw=(1,0) -> contributes (zr0, 0)
        // lane1 of acc currently zi0*1... must not include it: zero it via mul by (1,0):
        // instead accumulate from zero and include w=0 through the table.
        acc = 0;
#pragma unroll
        for (int w = 0; w < WM; w++)
            acc = f2fma(zw[w], tw2[w][x], acc);
        float a, bh; up2(acc, a, bh);
        orow[(size_t)x * CO] = a + bh;
        if (x >= 1 && x <= 63)
            orow[(size_t)(128 - x) * CO] = a - bh;
    }
}

// ---------------------------------------------------------------------------
extern "C" void kernel_launch(void* const* d_in, const int* in_sizes, int n_in,
                              void* d_out, int out_size) {
    const float*  X   = (const float*) d_in[0];
    const float2* ko0 = (const float2*)d_in[1];
    const float2* ki0 = (const float2*)d_in[2];
    const float2* ko1 = (const float2*)d_in[3];
    const float2* ki1 = (const float2*)d_in[4];
    float* out = (float*)d_out;

    s_kernel<<<dim3(HM * DEG, 8), 256>>>(ko0, ki0, 0);
    s_kernel<<<dim3(WM * DEG, 8), 256>>>(ko1, ki1, 1);
    k_kernel<<<dim3(NHW, 64), 256>>>();
    fwdW_kernel<<<BATCH * NHH, 128>>>(X);
    fwdH_kernel<<<BATCH * WM, 1024>>>();
    mix_kernel<<<NHW, 512>>>();
    invH_kernel<<<dim3(BATCH * WM, 4), 512>>>();
    invW_kernel<<<BATCH * NHH, 128>>>(out);
}

// round 4
// speedup vs baseline: 1.8040x; 1.0093x over previous
#include <cuda_runtime.h>
#include <math.h>

// ---------------------------------------------------------------------------
// TensorizedSpectralConv: B=32, H=W=128, C=128, modes 32x17, deg 2, rank 64
// Round 3: K-on-the-fly mix (g_K/k_kernel eliminated), fwdW software pipeline,
// interleaved u64 X1, merged s kernels.
// ---------------------------------------------------------------------------

#define BATCH 32
#define NHH   128
#define NWW   128
#define CI    128
#define CO    128
#define WM    17
#define HM    32
#define DEG   2
#define RANK  64
#define NHW   (HM*WM)   // 544

typedef unsigned long long u64;

__device__ u64    g_X1[BATCH*WM*NHH*CI];     // 71.3 MB  [b][w][y][c] (re,im)
__device__ float4 g_S0[HM*CO*CI];            //  8.4 MB  (d0.re,d0.im,d1.re,d1.im)
__device__ float4 g_S1[WM*CO*CI];            //  4.5 MB
__device__ float2 g_Xf[NHW*BATCH*CI];        // 17.8 MB  [h][w][b][c]
__device__ float2 g_Yf[NHW*BATCH*CO];        // 17.8 MB  [h][w][b][i]
__device__ float2 g_Z [BATCH*NHH*WM*CO];     // 71.3 MB  [b][y][w][i]

__device__ __forceinline__ u64 pk2(float x, float y) {
    u64 r; asm("mov.b64 %0,{%1,%2};" : "=l"(r) : "f"(x), "f"(y)); return r;
}
__device__ __forceinline__ void up2(u64 v, float& x, float& y) {
    asm("mov.b64 {%0,%1},%2;" : "=f"(x), "=f"(y) : "l"(v));
}
__device__ __forceinline__ u64 f2fma(u64 a, u64 b, u64 c) {
    u64 d; asm("fma.rn.f32x2 %0,%1,%2,%3;" : "=l"(d) : "l"(a), "l"(b), "l"(c)); return d;
}

__device__ __forceinline__ float2 cfma(float2 a, float2 b, float2 acc) {
    acc.x = fmaf(a.x, b.x, acc.x);
    acc.x = fmaf(-a.y, b.y, acc.x);
    acc.y = fmaf(a.x, b.y, acc.y);
    acc.y = fmaf(a.y, b.x, acc.y);
    return acc;
}

// ---------------------------------------------------------------------------
// S build (both axes in one launch): block per (axis, mode, d, i-chunk-of-16).
// blockIdx.x in [0, HM*DEG) -> axis 0; [HM*DEG, HM*DEG+WM*DEG) -> axis 1.
// ---------------------------------------------------------------------------
__global__ void __launch_bounds__(256) s_kernel(const float2* __restrict__ ko0,
                                                const float2* __restrict__ ki0,
                                                const float2* __restrict__ ko1,
                                                const float2* __restrict__ ki1) {
    int which = (blockIdx.x >= HM * DEG);
    int hd = which ? (blockIdx.x - HM * DEG) : blockIdx.x;
    const float2* ko = which ? ko1 : ko0;
    const float2* ki = which ? ki1 : ki0;
    float4* S = which ? g_S1 : g_S0;
    int h  = hd >> 1;
    int d  = hd & 1;
    int i0 = blockIdx.y * 16;
    __shared__ float2 kis[128][33];
    __shared__ float2 kos[16][33];
    int tid = threadIdx.x;
    int j = tid & 127, ih = tid >> 7;

    float2 acc[8];
#pragma unroll
    for (int ii = 0; ii < 8; ii++) acc[ii] = make_float2(0.f, 0.f);

    for (int r0 = 0; r0 < RANK; r0 += 32) {
        __syncthreads();
        for (int t = tid; t < 128 * 32; t += 256) {
            int jj = t >> 5, r = t & 31;
            kis[jj][r] = ki[((h * CI + jj) * DEG + d) * RANK + r0 + r];
        }
        for (int t = tid; t < 16 * 32; t += 256) {
            int ii = t >> 5, r = t & 31;
            kos[ii][r] = ko[((h * CO + i0 + ii) * DEG + d) * RANK + r0 + r];
        }
        __syncthreads();
        for (int r = 0; r < 32; r++) {
            float2 bj = kis[j][r];
#pragma unroll
            for (int ii = 0; ii < 8; ii++)
                acc[ii] = cfma(kos[ih * 8 + ii][r], bj, acc[ii]);
        }
    }
#pragma unroll
    for (int ii = 0; ii < 8; ii++) {
        int i = i0 + ih * 8 + ii;
        ((float2*)&S[(size_t)(h * CO + i) * CI + j])[d] = acc[ii];
    }
}

// ---------------------------------------------------------------------------
// Forward W DFT (real input, 17 modes), pair symmetry + f32x2, depth-2 pipeline.
// Block: (b, y-pair-of-rows); 256 threads = 2 y x 128 c.
// ---------------------------------------------------------------------------
__global__ void __launch_bounds__(256) fwdW_kernel(const float* __restrict__ X) {
    __shared__ u64 tw2[17][65];   // (cos(2pi w x/128), -sin(...)), x in [0,64]
    int tid = threadIdx.x;
    for (int t = tid; t < 17 * 65; t += 256) {
        int w = t / 65, x = t % 65;
        float s, c;
        sincospif((float)(w * x) / 64.0f, &s, &c);
        tw2[w][x] = pk2(c, -s);
    }
    __syncthreads();

    int c = tid & 127, ys = tid >> 7;
    int b = blockIdx.x >> 6;
    int y = ((blockIdx.x & 63) << 1) | ys;
    const float* base = X + ((size_t)(b * NHH + y) * NWW) * CI + c;

    float v0  = base[0];
    float v64 = base[64 * CI];
    u64 acc[WM];
#pragma unroll
    for (int w = 0; w < WM; w++)
        acc[w] = pk2(v0 + ((w & 1) ? -v64 : v64), 0.f);

    float a0 = base[1 * CI],  b0 = base[127 * CI];
    float a1 = base[2 * CI],  b1 = base[126 * CI];
    for (int x = 1; x < 63; x += 2) {
        float a2 = base[(x + 2) * CI];
        float b2 = base[(126 - x) * CI];
        float a3 = 0.f, b3 = 0.f;
        if (x + 3 < 64) { a3 = base[(x + 3) * CI]; b3 = base[(125 - x) * CI]; }
        u64 sd0 = pk2(a0 + b0, a0 - b0);
        u64 sd1 = pk2(a1 + b1, a1 - b1);
#pragma unroll
        for (int w = 0; w < WM; w++)
            acc[w] = f2fma(sd0, tw2[w][x], acc[w]);
#pragma unroll
        for (int w = 0; w < WM; w++)
            acc[w] = f2fma(sd1, tw2[w][x + 1], acc[w]);
        a0 = a2; b0 = b2; a1 = a3; b1 = b3;
    }
    {   // tail x = 63 (loaded into a0/b0 on the last iteration)
        u64 sd = pk2(a0 + b0, a0 - b0);
#pragma unroll
        for (int w = 0; w < WM; w++)
            acc[w] = f2fma(sd, tw2[w][63], acc[w]);
    }

    u64* dst = g_X1 + ((size_t)b * WM * NHH + y) * CI + c;
#pragma unroll
    for (int w = 0; w < WM; w++) dst[(size_t)w * NHH * CI] = acc[w];
}

// ---------------------------------------------------------------------------
// Forward H DFT (32 kept modes), pair symmetry over y + f32x2.
// Block per (b,w); 1024 threads = 32 h x 32 lanes; thread owns 4 channels.
// ---------------------------------------------------------------------------
__global__ void __launch_bounds__(1024) fwdH_kernel() {
    __shared__ u64 sn[21][128];
    __shared__ u64 dm[21][128];
    __shared__ u64 twcc[128];   // (cos, cos)
    __shared__ u64 twss[128];   // (sin, sin)
    int tid = threadIdx.x;
    if (tid < 128) {
        float s, c;
        sincospif((float)tid / 64.0f, &s, &c);
        twcc[tid] = pk2(c, c);
        twss[tid] = pk2(s, s);
    }
    int b = blockIdx.x / WM, w = blockIdx.x % WM;
    int lane = tid & 31, h = tid >> 5;
    int m = (h < 16) ? h : (96 + h);
    const u64* src = g_X1 + ((size_t)b * WM + w) * NHH * CI;

    // init: acc = x0 + (-1)^m * x64
    float sgn = (h & 1) ? -1.f : 1.f;
    u64 acc[4];
#pragma unroll
    for (int q = 0; q < 4; q++) {
        int c = lane + 32 * q;
        float r0, i0, r6, i6;
        up2(src[c], r0, i0);
        up2(src[64 * CI + c], r6, i6);
        acc[q] = pk2(fmaf(sgn, r6, r0), fmaf(sgn, i6, i0));
    }

    for (int chunk = 0; chunk < 3; chunk++) {
        int ypb = 1 + chunk * 21;
        __syncthreads();
        for (int t = tid; t < 21 * 128; t += 1024) {
            int yy = t >> 7, cc = t & 127;
            int yp = ypb + yy;
            float ar, ai, br, bi;
            up2(src[(size_t)yp * CI + cc], ar, ai);
            up2(src[(size_t)(128 - yp) * CI + cc], br, bi);
            sn[yy][cc] = pk2(ar + br, ai + bi);
            dm[yy][cc] = pk2(ai - bi, -(ar - br));
        }
        __syncthreads();
#pragma unroll 3
        for (int yy = 0; yy < 21; yy++) {
            int idx = (m * (ypb + yy)) & 127;
            u64 cc = twcc[idx], ss = twss[idx];
#pragma unroll
            for (int q = 0; q < 4; q++) {
                int c = lane + 32 * q;
                acc[q] = f2fma(sn[yy][c], cc, acc[q]);
                acc[q] = f2fma(dm[yy][c], ss, acc[q]);
            }
        }
    }
    u64* dst = (u64*)g_Xf + ((size_t)(h * WM + w) * BATCH + b) * CI;
#pragma unroll
    for (int q = 0; q < 4; q++) dst[lane + 32 * q] = acc[q];
}

// ---------------------------------------------------------------------------
// Mode mix with K computed on the fly from S0/S1 (L2-resident):
// per (h,w), Yf[b,i] = sum_j K[i,j] Xf[b,j],
// K[i,j] = (S0d0*S1d0 + S0d1*S1d1) / 16384.
// 512 threads: thread owns (i, 8 b's).
// ---------------------------------------------------------------------------
__global__ void __launch_bounds__(512) mix_kernel() {
    __shared__ float2 Ksm[16][130];
    __shared__ float2 xsm[32][17];
    int tid = threadIdx.x;
    int hw = blockIdx.x;
    int h = hw / WM, w = hw % WM;
    int i = tid & 127, bq = tid >> 7;
    const float4* A  = g_S0 + (size_t)h * CO * CI;
    const float4* Bm = g_S1 + (size_t)w * CO * CI;
    const float2* Xb = g_Xf + (size_t)hw * BATCH * CI;
    const float SCALE = 1.0f / 16384.0f;

    float2 acc[8];
#pragma unroll
    for (int bb = 0; bb < 8; bb++) acc[bb] = make_float2(0.f, 0.f);

    for (int j0 = 0; j0 < CI; j0 += 16) {
        __syncthreads();
        for (int t = tid; t < 128 * 16; t += 512) {
            int ii = t >> 4, jj = t & 15;
            int e = ii * CI + j0 + jj;
            float4 a = A[e];
            float4 bv = Bm[e];
            float kr = a.x * bv.x - a.y * bv.y + a.z * bv.z - a.w * bv.w;
            float ki = a.x * bv.y + a.y * bv.x + a.z * bv.w + a.w * bv.z;
            Ksm[jj][ii] = make_float2(kr * SCALE, ki * SCALE);
        }
        {
            int bb = tid >> 4, jj = tid & 15;
            xsm[bb][jj] = Xb[bb * CI + j0 + jj];
        }
        __syncthreads();
        for (int jj = 0; jj < 16; jj++) {
            float2 kv = Ksm[jj][i];
#pragma unroll
            for (int bb = 0; bb < 8; bb++)
                acc[bb] = cfma(kv, xsm[bq * 8 + bb][jj], acc[bb]);
        }
    }
    float2* dst = g_Yf + (size_t)hw * BATCH * CO;
#pragma unroll
    for (int bb = 0; bb < 8; bb++) dst[(bq * 8 + bb) * CO + i] = acc[bb];
}

// ---------------------------------------------------------------------------
// Inverse H: Z[b,y,w,i] = sum_h Yf[h,w,b,i] e^{+2pi i m(h) y/128}.
// Mode-pair symmetry + f32x2. Grid (b*17+w, yq); 512 thr = (i, 4 ysub), 8 y each.
// ---------------------------------------------------------------------------
__global__ void __launch_bounds__(512) invH_kernel() {
    __shared__ u64 ys[32][128];
    __shared__ u64 twcc[128];
    __shared__ u64 twss[128];
    int tid = threadIdx.x;
    if (tid < 128) {
        float s, c;
        sincospif((float)tid / 64.0f, &s, &c);
        twcc[tid] = pk2(c, c);
        twss[tid] = pk2(s, s);
    }
    int hw = blockIdx.x;
    int b = hw / WM, w = hw % WM;
    int y0 = blockIdx.y * 32;
    int i = tid & 127, ysub = tid >> 7;
    int yb = y0 + ysub * 8;

    const u64* Ysrc = (const u64*)g_Yf;
    for (int t = tid; t < 32 * 128; t += 512) {
        int h = t >> 7, ii = t & 127;
        ys[h][ii] = Ysrc[((size_t)(h * WM + w) * BATCH + b) * CO + ii];
    }
    __syncthreads();

    u64 acc[8];
    {   // m = 0
        u64 v0 = ys[0][i];
#pragma unroll
        for (int k = 0; k < 8; k++) acc[k] = v0;
    }
    {   // m = -16 (h=16): contrib = v * e^{-i 2pi 16 y/128}
        u64 v = ys[16][i];
        float vr, vi; up2(v, vr, vi);
        u64 vs = pk2(vi, -vr);
        int idx = (16 * yb) & 127;
#pragma unroll
        for (int k = 0; k < 8; k++) {
            acc[k] = f2fma(v,  twcc[idx], acc[k]);
            acc[k] = f2fma(vs, twss[idx], acc[k]);
            idx = (idx + 16) & 127;
        }
    }
#pragma unroll 3
    for (int m = 1; m < 16; m++) {
        u64 y1 = ys[m][i];
        u64 y2 = ys[32 - m][i];
        float ar, ai, br, bi;
        up2(y1, ar, ai); up2(y2, br, bi);
        u64 s  = pk2(ar + br, ai + bi);
        u64 dp = pk2(-(ai - bi), ar - br);
        int idx = (m * yb) & 127;
#pragma unroll
        for (int k = 0; k < 8; k++) {
            acc[k] = f2fma(s,  twcc[idx], acc[k]);
            acc[k] = f2fma(dp, twss[idx], acc[k]);
            idx = (idx + m) & 127;
        }
    }
    u64* Zd = (u64*)g_Z;
#pragma unroll
    for (int k = 0; k < 8; k++) {
        int y = yb + k;
        Zd[((size_t)(b * NHH + y) * WM + w) * CO + i] = acc[k];
    }
}

// ---------------------------------------------------------------------------
// Inverse W (hermitian, real output), pair symmetry + f32x2.
// Block per (b,y); 128 threads = i.
// ---------------------------------------------------------------------------
__global__ void __launch_bounds__(128) invW_kernel(float* __restrict__ out) {
    __shared__ u64 tw2[17][65];   // (cos(2pi w x/128), -sin(...))
    int tid = threadIdx.x;
    for (int t = tid; t < 17 * 65; t += 128) {
        int w = t / 65, x = t % 65;
        float s, c;
        sincospif((float)(w * x) / 64.0f, &s, &c);
        tw2[w][x] = pk2(c, -s);
    }
    __syncthreads();

    int b = blockIdx.x >> 7, y = blockIdx.x & 127;
    const float2* zrow = g_Z + (size_t)(b * NHH + y) * WM * CO;

    u64 zw[WM];
#pragma unroll
    for (int w = 0; w < WM; w++) {
        float2 v = zrow[w * CO + tid];
        float cw = (w == 0) ? 1.0f : 2.0f;
        zw[w] = pk2(v.x * cw, v.y * cw);
    }

    float* orow = out + (size_t)(b * NHH + y) * NWW * CO + tid;
    for (int x = 0; x <= 64; x++) {
        u64 acc = 0;
#pragma unroll
        for (int w = 0; w < WM; w++)
            acc = f2fma(zw[w], tw2[w][x], acc);
        float a, bh; up2(acc, a, bh);
        orow[(size_t)x * CO] = a + bh;
        if (x >= 1 && x <= 63)
            orow[(size_t)(128 - x) * CO] = a - bh;
    }
}

// ---------------------------------------------------------------------------
extern "C" void kernel_launch(void* const* d_in, const int* in_sizes, int n_in,
                              void* d_out, int out_size) {
    const float*  X   = (const float*) d_in[0];
    const float2* ko0 = (const float2*)d_in[1];
    const float2* ki0 = (const float2*)d_in[2];
    const float2* ko1 = (const float2*)d_in[3];
    const float2* ki1 = (const float2*)d_in[4];
    float* out = (float*)d_out;

    s_kernel<<<dim3(HM * DEG + WM * DEG, 8), 256>>>(ko0, ki0, ko1, ki1);
    fwdW_kernel<<<BATCH * 64, 256>>>(X);
    fwdH_kernel<<<BATCH * WM, 1024>>>();
    mix_kernel<<<NHW, 512>>>();
    invH_kernel<<<dim3(BATCH * WM, 4), 512>>>();
    invW_kernel<<<BATCH * NHH, 128>>>(out);
}

// round 5
// speedup vs baseline: 2.0537x; 1.1384x over previous
#include <cuda_runtime.h>
#include <math.h>

// ---------------------------------------------------------------------------
// TensorizedSpectralConv: B=32, H=W=128, C=128, modes 32x17, deg 2, rank 64
// Round 4: f32x2 P/Q mix GEMM, even/odd radix split in fwdW and invW.
// ---------------------------------------------------------------------------

#define BATCH 32
#define NHH   128
#define NWW   128
#define CI    128
#define CO    128
#define WM    17
#define HM    32
#define DEG   2
#define RANK  64
#define NHW   (HM*WM)   // 544

typedef unsigned long long u64;

__device__ u64    g_X1[BATCH*WM*NHH*CI];     // 71.3 MB  [b][w][y][c] (re,im)
__device__ float4 g_S0[HM*CO*CI];            //  8.4 MB  (d0.re,d0.im,d1.re,d1.im)
__device__ float4 g_S1[WM*CO*CI];            //  4.5 MB
__device__ float2 g_Xf[NHW*BATCH*CI];        // 17.8 MB  [h][w][b][c]
__device__ float2 g_Yf[NHW*BATCH*CO];        // 17.8 MB  [h][w][b][i]
__device__ float2 g_Z [BATCH*NHH*WM*CO];     // 71.3 MB  [b][y][w][i]

__device__ __forceinline__ u64 pk2(float x, float y) {
    u64 r; asm("mov.b64 %0,{%1,%2};" : "=l"(r) : "f"(x), "f"(y)); return r;
}
__device__ __forceinline__ void up2(u64 v, float& x, float& y) {
    asm("mov.b64 {%0,%1},%2;" : "=f"(x), "=f"(y) : "l"(v));
}
__device__ __forceinline__ u64 f2fma(u64 a, u64 b, u64 c) {
    u64 d; asm("fma.rn.f32x2 %0,%1,%2,%3;" : "=l"(d) : "l"(a), "l"(b), "l"(c)); return d;
}

__device__ __forceinline__ float2 cfma(float2 a, float2 b, float2 acc) {
    acc.x = fmaf(a.x, b.x, acc.x);
    acc.x = fmaf(-a.y, b.y, acc.x);
    acc.y = fmaf(a.x, b.y, acc.y);
    acc.y = fmaf(a.y, b.x, acc.y);
    return acc;
}

// ---------------------------------------------------------------------------
// S build (both axes in one launch): block per (axis, mode, d, i-chunk-of-16).
// ---------------------------------------------------------------------------
__global__ void __launch_bounds__(256) s_kernel(const float2* __restrict__ ko0,
                                                const float2* __restrict__ ki0,
                                                const float2* __restrict__ ko1,
                                                const float2* __restrict__ ki1) {
    int which = (blockIdx.x >= HM * DEG);
    int hd = which ? (blockIdx.x - HM * DEG) : blockIdx.x;
    const float2* ko = which ? ko1 : ko0;
    const float2* ki = which ? ki1 : ki0;
    float4* S = which ? g_S1 : g_S0;
    int h  = hd >> 1;
    int d  = hd & 1;
    int i0 = blockIdx.y * 16;
    __shared__ float2 kis[128][33];
    __shared__ float2 kos[16][33];
    int tid = threadIdx.x;
    int j = tid & 127, ih = tid >> 7;

    float2 acc[8];
#pragma unroll
    for (int ii = 0; ii < 8; ii++) acc[ii] = make_float2(0.f, 0.f);

    for (int r0 = 0; r0 < RANK; r0 += 32) {
        __syncthreads();
        for (int t = tid; t < 128 * 32; t += 256) {
            int jj = t >> 5, r = t & 31;
            kis[jj][r] = ki[((h * CI + jj) * DEG + d) * RANK + r0 + r];
        }
        for (int t = tid; t < 16 * 32; t += 256) {
            int ii = t >> 5, r = t & 31;
            kos[ii][r] = ko[((h * CO + i0 + ii) * DEG + d) * RANK + r0 + r];
        }
        __syncthreads();
        for (int r = 0; r < 32; r++) {
            float2 bj = kis[j][r];
#pragma unroll
            for (int ii = 0; ii < 8; ii++)
                acc[ii] = cfma(kos[ih * 8 + ii][r], bj, acc[ii]);
        }
    }
#pragma unroll
    for (int ii = 0; ii < 8; ii++) {
        int i = i0 + ih * 8 + ii;
        ((float2*)&S[(size_t)(h * CO + i) * CI + j])[d] = acc[ii];
    }
}

// ---------------------------------------------------------------------------
// Forward W DFT (real input, 17 modes). Even/odd split over x+64, pair fold
// over 64-x, f32x2. Block: 2 y-rows; 256 threads = 2 y x 128 c.
// even w=2e:  accE[e] += (sE*cos, -dE*sin)   angle 2pi*w*u/128
// odd  w=2o+1: accO[o] += (dO*cos, -sO*sin)
// ---------------------------------------------------------------------------
__global__ void __launch_bounds__(256) fwdW_kernel(const float* __restrict__ X) {
    __shared__ u64 tw2[17][33];   // (cos(2pi w u/128), -sin(...)), u in [0,32]
    int tid = threadIdx.x;
    for (int t = tid; t < 17 * 33; t += 256) {
        int w = t / 33, u = t % 33;
        float s, c;
        sincospif((float)(w * u) / 64.0f, &s, &c);
        tw2[w][u] = pk2(c, -s);
    }
    __syncthreads();

    int c = tid & 127, ys = tid >> 7;
    int b = blockIdx.x >> 6;
    int y = ((blockIdx.x & 63) << 1) | ys;
    const float* base = X + ((size_t)(b * NHH + y) * NWW) * CI + c;

    float v0  = base[0],       v32 = base[32 * CI];
    float v64 = base[64 * CI], v96 = base[96 * CI];
    float pE0  = v0 + v64,  pO0  = v0 - v64;
    float pE32 = v32 + v96, pO32 = v32 - v96;

    u64 accE[9], accO[8];
#pragma unroll
    for (int e = 0; e < 9; e++)
        accE[e] = pk2(pE0 + ((e & 1) ? -pE32 : pE32), 0.f);
#pragma unroll
    for (int o = 0; o < 8; o++)
        accO[o] = pk2(pO0, (o & 1) ? pO32 : -pO32);

    for (int u = 1; u < 32; u++) {
        float va = base[u * CI];
        float vb = base[(u + 64) * CI];
        float vc = base[(64 - u) * CI];
        float vd = base[(128 - u) * CI];
        float pEu = va + vb, pOu = va - vb;
        float pEv = vc + vd, pOv = vc - vd;
        u64 sdE = pk2(pEu + pEv, pEu - pEv);
        u64 dsO = pk2(pOu - pOv, pOu + pOv);
#pragma unroll
        for (int e = 0; e < 9; e++)
            accE[e] = f2fma(sdE, tw2[2 * e][u], accE[e]);
#pragma unroll
        for (int o = 0; o < 8; o++)
            accO[o] = f2fma(dsO, tw2[2 * o + 1][u], accO[o]);
    }

    u64* dst = g_X1 + ((size_t)b * WM * NHH + y) * CI + c;
#pragma unroll
    for (int w = 0; w < WM; w++)
        dst[(size_t)w * NHH * CI] = (w & 1) ? accO[w >> 1] : accE[w >> 1];
}

// ---------------------------------------------------------------------------
// Forward H DFT (32 kept modes), pair symmetry over y + f32x2. Unchanged.
// ---------------------------------------------------------------------------
__global__ void __launch_bounds__(1024) fwdH_kernel() {
    __shared__ u64 sn[21][128];
    __shared__ u64 dm[21][128];
    __shared__ u64 twcc[128];
    __shared__ u64 twss[128];
    int tid = threadIdx.x;
    if (tid < 128) {
        float s, c;
        sincospif((float)tid / 64.0f, &s, &c);
        twcc[tid] = pk2(c, c);
        twss[tid] = pk2(s, s);
    }
    int b = blockIdx.x / WM, w = blockIdx.x % WM;
    int lane = tid & 31, h = tid >> 5;
    int m = (h < 16) ? h : (96 + h);
    const u64* src = g_X1 + ((size_t)b * WM + w) * NHH * CI;

    float sgn = (h & 1) ? -1.f : 1.f;
    u64 acc[4];
#pragma unroll
    for (int q = 0; q < 4; q++) {
        int c = lane + 32 * q;
        float r0, i0, r6, i6;
        up2(src[c], r0, i0);
        up2(src[64 * CI + c], r6, i6);
        acc[q] = pk2(fmaf(sgn, r6, r0), fmaf(sgn, i6, i0));
    }

    for (int chunk = 0; chunk < 3; chunk++) {
        int ypb = 1 + chunk * 21;
        __syncthreads();
        for (int t = tid; t < 21 * 128; t += 1024) {
            int yy = t >> 7, cc = t & 127;
            int yp = ypb + yy;
            float ar, ai, br, bi;
            up2(src[(size_t)yp * CI + cc], ar, ai);
            up2(src[(size_t)(128 - yp) * CI + cc], br, bi);
            sn[yy][cc] = pk2(ar + br, ai + bi);
            dm[yy][cc] = pk2(ai - bi, -(ar - br));
        }
        __syncthreads();
#pragma unroll 3
        for (int yy = 0; yy < 21; yy++) {
            int idx = (m * (ypb + yy)) & 127;
            u64 cc = twcc[idx], ss = twss[idx];
#pragma unroll
            for (int q = 0; q < 4; q++) {
                int c = lane + 32 * q;
                acc[q] = f2fma(sn[yy][c], cc, acc[q]);
                acc[q] = f2fma(dm[yy][c], ss, acc[q]);
            }
        }
    }
    u64* dst = (u64*)g_Xf + ((size_t)(h * WM + w) * BATCH + b) * CI;
#pragma unroll
    for (int q = 0; q < 4; q++) dst[lane + 32 * q] = acc[q];
}

// ---------------------------------------------------------------------------
// Mode mix, f32x2 with split P/Q accumulators.
// per (h,w): Yf[b,i] = sum_j K[i,j] Xf[b,j], K from S0/S1 on the fly.
// 512 threads: thread (i = tid&127, bq = tid>>7) owns 8 b's.
// accP += x*(kr,kr); accQ += x*(ki,ki); final (Pr-Qi, Pi+Qr).
// ---------------------------------------------------------------------------
__global__ void __launch_bounds__(512) mix_kernel() {
    __shared__ ulonglong2 xsm[32][64];   // 32KB: x[b][j] pairs (j even/odd)
    __shared__ float4 Ksm[4][129];       // 8.2KB: [jj2][i] = (kr0,ki0,kr1,ki1)
    int tid = threadIdx.x;
    int hw = blockIdx.x;
    int h = hw / WM, w = hw % WM;
    int i = tid & 127, bq = tid >> 7;
    const float4* A  = g_S0 + (size_t)h * CO * CI;
    const float4* Bm = g_S1 + (size_t)w * CO * CI;
    const u64* Xb = (const u64*)g_Xf + (size_t)hw * BATCH * CI;
    const float SCALE = 1.0f / 16384.0f;

    // stage all x once (u64 per (b,j))
    u64* xflat = (u64*)xsm;
    for (int t = tid; t < 32 * 128; t += 512)
        xflat[t] = Xb[(t >> 7) * CI + (t & 127)];

    // K staging ownership: one (ii, jj2) per thread per chunk
    int kjj2 = tid & 3, kii = tid >> 2;
    int e0 = kii * CI + 2 * kjj2;
    float4 pa0 = A[e0], pa1 = A[e0 + 1];
    float4 pb0 = Bm[e0], pb1 = Bm[e0 + 1];

    u64 accP[8], accQ[8];
#pragma unroll
    for (int bb = 0; bb < 8; bb++) { accP[bb] = 0; accQ[bb] = 0; }

    for (int chunk = 0; chunk < 16; chunk++) {
        __syncthreads();   // Ksm free to overwrite; x staged (chunk 0)
        {
            float kr0 = pa0.x * pb0.x - pa0.y * pb0.y + pa0.z * pb0.z - pa0.w * pb0.w;
            float ki0 = pa0.x * pb0.y + pa0.y * pb0.x + pa0.z * pb0.w + pa0.w * pb0.z;
            float kr1 = pa1.x * pb1.x - pa1.y * pb1.y + pa1.z * pb1.z - pa1.w * pb1.w;
            float ki1 = pa1.x * pb1.y + pa1.y * pb1.x + pa1.z * pb1.w + pa1.w * pb1.z;
            Ksm[kjj2][kii] = make_float4(kr0 * SCALE, ki0 * SCALE, kr1 * SCALE, ki1 * SCALE);
        }
        if (chunk < 15) {
            int e = kii * CI + (chunk + 1) * 8 + 2 * kjj2;
            pa0 = A[e]; pa1 = A[e + 1]; pb0 = Bm[e]; pb1 = Bm[e + 1];
        }
        __syncthreads();
#pragma unroll
        for (int jj2 = 0; jj2 < 4; jj2++) {
            float4 kk = Ksm[jj2][i];
            u64 kc0 = pk2(kk.x, kk.x), ks0 = pk2(kk.y, kk.y);
            u64 kc1 = pk2(kk.z, kk.z), ks1 = pk2(kk.w, kk.w);
            int jidx = chunk * 4 + jj2;
#pragma unroll
            for (int bb = 0; bb < 8; bb++) {
                ulonglong2 xx = xsm[bq * 8 + bb][jidx];
                accP[bb] = f2fma(xx.x, kc0, accP[bb]);
                accQ[bb] = f2fma(xx.x, ks0, accQ[bb]);
                accP[bb] = f2fma(xx.y, kc1, accP[bb]);
                accQ[bb] = f2fma(xx.y, ks1, accQ[bb]);
            }
        }
    }
    float2* dst = g_Yf + (size_t)hw * BATCH * CO;
#pragma unroll
    for (int bb = 0; bb < 8; bb++) {
        float pr, pi, qr, qi;
        up2(accP[bb], pr, pi);
        up2(accQ[bb], qr, qi);
        dst[(bq * 8 + bb) * CO + i] = make_float2(pr - qi, pi + qr);
    }
}

// ---------------------------------------------------------------------------
// Inverse H: Z[b,y,w,i] = sum_h Yf[h,w,b,i] e^{+2pi i m(h) y/128}. Unchanged.
// ---------------------------------------------------------------------------
__global__ void __launch_bounds__(512) invH_kernel() {
    __shared__ u64 ys[32][128];
    __shared__ u64 twcc[128];
    __shared__ u64 twss[128];
    int tid = threadIdx.x;
    if (tid < 128) {
        float s, c;
        sincospif((float)tid / 64.0f, &s, &c);
        twcc[tid] = pk2(c, c);
        twss[tid] = pk2(s, s);
    }
    int hw = blockIdx.x;
    int b = hw / WM, w = hw % WM;
    int y0 = blockIdx.y * 32;
    int i = tid & 127, ysub = tid >> 7;
    int yb = y0 + ysub * 8;

    const u64* Ysrc = (const u64*)g_Yf;
    for (int t = tid; t < 32 * 128; t += 512) {
        int h = t >> 7, ii = t & 127;
        ys[h][ii] = Ysrc[((size_t)(h * WM + w) * BATCH + b) * CO + ii];
    }
    __syncthreads();

    u64 acc[8];
    {   // m = 0
        u64 v0 = ys[0][i];
#pragma unroll
        for (int k = 0; k < 8; k++) acc[k] = v0;
    }
    {   // m = -16 (h=16)
        u64 v = ys[16][i];
        float vr, vi; up2(v, vr, vi);
        u64 vs = pk2(vi, -vr);
        int idx = (16 * yb) & 127;
#pragma unroll
        for (int k = 0; k < 8; k++) {
            acc[k] = f2fma(v,  twcc[idx], acc[k]);
            acc[k] = f2fma(vs, twss[idx], acc[k]);
            idx = (idx + 16) & 127;
        }
    }
#pragma unroll 3
    for (int m = 1; m < 16; m++) {
        u64 y1 = ys[m][i];
        u64 y2 = ys[32 - m][i];
        float ar, ai, br, bi;
        up2(y1, ar, ai); up2(y2, br, bi);
        u64 s  = pk2(ar + br, ai + bi);
        u64 dp = pk2(-(ai - bi), ar - br);
        int idx = (m * yb) & 127;
#pragma unroll
        for (int k = 0; k < 8; k++) {
            acc[k] = f2fma(s,  twcc[idx], acc[k]);
            acc[k] = f2fma(dp, twss[idx], acc[k]);
            idx = (idx + m) & 127;
        }
    }
    u64* Zd = (u64*)g_Z;
#pragma unroll
    for (int k = 0; k < 8; k++) {
        int y = yb + k;
        Zd[((size_t)(b * NHH + y) * WM + w) * CO + i] = acc[k];
    }
}

// ---------------------------------------------------------------------------
// Inverse W (hermitian, real output), even/odd + pair symmetry, f32x2.
// Block per (b,y); 128 threads = i. accE/accO at x give acc(x), acc(x+64).
// out[x]=a+bh, out[128-x]=a-bh.
// ---------------------------------------------------------------------------
__global__ void __launch_bounds__(128) invW_kernel(float* __restrict__ out) {
    __shared__ u64 tw2[17][33];   // (cos(2pi w x/128), -sin(...)), x in [0,32]
    int tid = threadIdx.x;
    for (int t = tid; t < 17 * 33; t += 128) {
        int w = t / 33, x = t % 33;
        float s, c;
        sincospif((float)(w * x) / 64.0f, &s, &c);
        tw2[w][x] = pk2(c, -s);
    }
    __syncthreads();

    int b = blockIdx.x >> 7, y = blockIdx.x & 127;
    const float2* zrow = g_Z + (size_t)(b * NHH + y) * WM * CO;

    u64 zw[WM];
#pragma unroll
    for (int w = 0; w < WM; w++) {
        float2 v = zrow[w * CO + tid];
        float cw = (w == 0) ? 1.0f : 2.0f;
        zw[w] = pk2(v.x * cw, v.y * cw);
    }

    float* orow = out + (size_t)(b * NHH + y) * NWW * CO + tid;
    for (int x = 0; x <= 32; x++) {
        u64 aE = 0, aO = 0;
#pragma unroll
        for (int e = 0; e < 9; e++)
            aE = f2fma(zw[2 * e], tw2[2 * e][x], aE);
#pragma unroll
        for (int o = 0; o < 8; o++)
            aO = f2fma(zw[2 * o + 1], tw2[2 * o + 1][x], aO);
        float eR, eI, oR, oI;
        up2(aE, eR, eI);
        up2(aO, oR, oI);
        float a0 = eR + oR, b0 = eI + oI;   // acc(x)
        float a1 = eR - oR, b1 = eI - oI;   // acc(x+64)
        if (x == 0) {
            orow[0]            = a0 + b0;
            orow[64 * CO]      = a1 + b1;
        } else if (x == 32) {
            orow[32 * CO]      = a0 + b0;
            orow[96 * CO]      = a1 + b1;
        } else {
            orow[(size_t)x * CO]          = a0 + b0;
            orow[(size_t)(128 - x) * CO]  = a0 - b0;
            orow[(size_t)(x + 64) * CO]   = a1 + b1;
            orow[(size_t)(64 - x) * CO]   = a1 - b1;
        }
    }
}

// ---------------------------------------------------------------------------
extern "C" void kernel_launch(void* const* d_in, const int* in_sizes, int n_in,
                              void* d_out, int out_size) {
    const float*  X   = (const float*) d_in[0];
    const float2* ko0 = (const float2*)d_in[1];
    const float2* ki0 = (const float2*)d_in[2];
    const float2* ko1 = (const float2*)d_in[3];
    const float2* ki1 = (const float2*)d_in[4];
    float* out = (float*)d_out;

    s_kernel<<<dim3(HM * DEG + WM * DEG, 8), 256>>>(ko0, ki0, ko1, ki1);
    fwdW_kernel<<<BATCH * 64, 256>>>(X);
    fwdH_kernel<<<BATCH * WM, 1024>>>();
    mix_kernel<<<NHW, 512>>>();
    invH_kernel<<<dim3(BATCH * WM, 4), 512>>>();
    invW_kernel<<<BATCH * NHH, 128>>>(out);
}

// round 6
// speedup vs baseline: 2.1117x; 1.0282x over previous
#include <cuda_runtime.h>
#include <math.h>

// ---------------------------------------------------------------------------
// TensorizedSpectralConv: B=32, H=W=128, C=128, modes 32x17, deg 2, rank 64
// Round 5: mix occupancy fix (no prefetch, launch_bounds(512,2)),
// invW split accumulator chains.
// ---------------------------------------------------------------------------

#define BATCH 32
#define NHH   128
#define NWW   128
#define CI    128
#define CO    128
#define WM    17
#define HM    32
#define DEG   2
#define RANK  64
#define NHW   (HM*WM)   // 544

typedef unsigned long long u64;

__device__ u64    g_X1[BATCH*WM*NHH*CI];     // 71.3 MB  [b][w][y][c] (re,im)
__device__ float4 g_S0[HM*CO*CI];            //  8.4 MB  (d0.re,d0.im,d1.re,d1.im)
__device__ float4 g_S1[WM*CO*CI];            //  4.5 MB
__device__ float2 g_Xf[NHW*BATCH*CI];        // 17.8 MB  [h][w][b][c]
__device__ float2 g_Yf[NHW*BATCH*CO];        // 17.8 MB  [h][w][b][i]
__device__ float2 g_Z [BATCH*NHH*WM*CO];     // 71.3 MB  [b][y][w][i]

__device__ __forceinline__ u64 pk2(float x, float y) {
    u64 r; asm("mov.b64 %0,{%1,%2};" : "=l"(r) : "f"(x), "f"(y)); return r;
}
__device__ __forceinline__ void up2(u64 v, float& x, float& y) {
    asm("mov.b64 {%0,%1},%2;" : "=f"(x), "=f"(y) : "l"(v));
}
__device__ __forceinline__ u64 f2fma(u64 a, u64 b, u64 c) {
    u64 d; asm("fma.rn.f32x2 %0,%1,%2,%3;" : "=l"(d) : "l"(a), "l"(b), "l"(c)); return d;
}
__device__ __forceinline__ u64 f2add(u64 a, u64 b) {
    u64 d; asm("add.rn.f32x2 %0,%1,%2;" : "=l"(d) : "l"(a), "l"(b)); return d;
}

__device__ __forceinline__ float2 cfma(float2 a, float2 b, float2 acc) {
    acc.x = fmaf(a.x, b.x, acc.x);
    acc.x = fmaf(-a.y, b.y, acc.x);
    acc.y = fmaf(a.x, b.y, acc.y);
    acc.y = fmaf(a.y, b.x, acc.y);
    return acc;
}

// ---------------------------------------------------------------------------
// S build (both axes in one launch): block per (axis, mode, d, i-chunk-of-16).
// ---------------------------------------------------------------------------
__global__ void __launch_bounds__(256) s_kernel(const float2* __restrict__ ko0,
                                                const float2* __restrict__ ki0,
                                                const float2* __restrict__ ko1,
                                                const float2* __restrict__ ki1) {
    int which = (blockIdx.x >= HM * DEG);
    int hd = which ? (blockIdx.x - HM * DEG) : blockIdx.x;
    const float2* ko = which ? ko1 : ko0;
    const float2* ki = which ? ki1 : ki0;
    float4* S = which ? g_S1 : g_S0;
    int h  = hd >> 1;
    int d  = hd & 1;
    int i0 = blockIdx.y * 16;
    __shared__ float2 kis[128][33];
    __shared__ float2 kos[16][33];
    int tid = threadIdx.x;
    int j = tid & 127, ih = tid >> 7;

    float2 acc[8];
#pragma unroll
    for (int ii = 0; ii < 8; ii++) acc[ii] = make_float2(0.f, 0.f);

    for (int r0 = 0; r0 < RANK; r0 += 32) {
        __syncthreads();
        for (int t = tid; t < 128 * 32; t += 256) {
            int jj = t >> 5, r = t & 31;
            kis[jj][r] = ki[((h * CI + jj) * DEG + d) * RANK + r0 + r];
        }
        for (int t = tid; t < 16 * 32; t += 256) {
            int ii = t >> 5, r = t & 31;
            kos[ii][r] = ko[((h * CO + i0 + ii) * DEG + d) * RANK + r0 + r];
        }
        __syncthreads();
        for (int r = 0; r < 32; r++) {
            float2 bj = kis[j][r];
#pragma unroll
            for (int ii = 0; ii < 8; ii++)
                acc[ii] = cfma(kos[ih * 8 + ii][r], bj, acc[ii]);
        }
    }
#pragma unroll
    for (int ii = 0; ii < 8; ii++) {
        int i = i0 + ih * 8 + ii;
        ((float2*)&S[(size_t)(h * CO + i) * CI + j])[d] = acc[ii];
    }
}

// ---------------------------------------------------------------------------
// Forward W DFT (real input, 17 modes). Even/odd split + pair fold, f32x2.
// ---------------------------------------------------------------------------
__global__ void __launch_bounds__(256) fwdW_kernel(const float* __restrict__ X) {
    __shared__ u64 tw2[17][33];   // (cos(2pi w u/128), -sin(...)), u in [0,32]
    int tid = threadIdx.x;
    for (int t = tid; t < 17 * 33; t += 256) {
        int w = t / 33, u = t % 33;
        float s, c;
        sincospif((float)(w * u) / 64.0f, &s, &c);
        tw2[w][u] = pk2(c, -s);
    }
    __syncthreads();

    int c = tid & 127, ys = tid >> 7;
    int b = blockIdx.x >> 6;
    int y = ((blockIdx.x & 63) << 1) | ys;
    const float* base = X + ((size_t)(b * NHH + y) * NWW) * CI + c;

    float v0  = base[0],       v32 = base[32 * CI];
    float v64 = base[64 * CI], v96 = base[96 * CI];
    float pE0  = v0 + v64,  pO0  = v0 - v64;
    float pE32 = v32 + v96, pO32 = v32 - v96;

    u64 accE[9], accO[8];
#pragma unroll
    for (int e = 0; e < 9; e++)
        accE[e] = pk2(pE0 + ((e & 1) ? -pE32 : pE32), 0.f);
#pragma unroll
    for (int o = 0; o < 8; o++)
        accO[o] = pk2(pO0, (o & 1) ? pO32 : -pO32);

    for (int u = 1; u < 32; u++) {
        float va = base[u * CI];
        float vb = base[(u + 64) * CI];
        float vc = base[(64 - u) * CI];
        float vd = base[(128 - u) * CI];
        float pEu = va + vb, pOu = va - vb;
        float pEv = vc + vd, pOv = vc - vd;
        u64 sdE = pk2(pEu + pEv, pEu - pEv);
        u64 dsO = pk2(pOu - pOv, pOu + pOv);
#pragma unroll
        for (int e = 0; e < 9; e++)
            accE[e] = f2fma(sdE, tw2[2 * e][u], accE[e]);
#pragma unroll
        for (int o = 0; o < 8; o++)
            accO[o] = f2fma(dsO, tw2[2 * o + 1][u], accO[o]);
    }

    u64* dst = g_X1 + ((size_t)b * WM * NHH + y) * CI + c;
#pragma unroll
    for (int w = 0; w < WM; w++)
        dst[(size_t)w * NHH * CI] = (w & 1) ? accO[w >> 1] : accE[w >> 1];
}

// ---------------------------------------------------------------------------
// Forward H DFT (32 kept modes), pair symmetry over y + f32x2.
// ---------------------------------------------------------------------------
__global__ void __launch_bounds__(1024) fwdH_kernel() {
    __shared__ u64 sn[21][128];
    __shared__ u64 dm[21][128];
    __shared__ u64 twcc[128];
    __shared__ u64 twss[128];
    int tid = threadIdx.x;
    if (tid < 128) {
        float s, c;
        sincospif((float)tid / 64.0f, &s, &c);
        twcc[tid] = pk2(c, c);
        twss[tid] = pk2(s, s);
    }
    int b = blockIdx.x / WM, w = blockIdx.x % WM;
    int lane = tid & 31, h = tid >> 5;
    int m = (h < 16) ? h : (96 + h);
    const u64* src = g_X1 + ((size_t)b * WM + w) * NHH * CI;

    float sgn = (h & 1) ? -1.f : 1.f;
    u64 acc[4];
#pragma unroll
    for (int q = 0; q < 4; q++) {
        int c = lane + 32 * q;
        float r0, i0, r6, i6;
        up2(src[c], r0, i0);
        up2(src[64 * CI + c], r6, i6);
        acc[q] = pk2(fmaf(sgn, r6, r0), fmaf(sgn, i6, i0));
    }

    for (int chunk = 0; chunk < 3; chunk++) {
        int ypb = 1 + chunk * 21;
        __syncthreads();
        for (int t = tid; t < 21 * 128; t += 1024) {
            int yy = t >> 7, cc = t & 127;
            int yp = ypb + yy;
            float ar, ai, br, bi;
            up2(src[(size_t)yp * CI + cc], ar, ai);
            up2(src[(size_t)(128 - yp) * CI + cc], br, bi);
            sn[yy][cc] = pk2(ar + br, ai + bi);
            dm[yy][cc] = pk2(ai - bi, -(ar - br));
        }
        __syncthreads();
#pragma unroll 3
        for (int yy = 0; yy < 21; yy++) {
            int idx = (m * (ypb + yy)) & 127;
            u64 cc = twcc[idx], ss = twss[idx];
#pragma unroll
            for (int q = 0; q < 4; q++) {
                int c = lane + 32 * q;
                acc[q] = f2fma(sn[yy][c], cc, acc[q]);
                acc[q] = f2fma(dm[yy][c], ss, acc[q]);
            }
        }
    }
    u64* dst = (u64*)g_Xf + ((size_t)(h * WM + w) * BATCH + b) * CI;
#pragma unroll
    for (int q = 0; q < 4; q++) dst[lane + 32 * q] = acc[q];
}

// ---------------------------------------------------------------------------
// Mode mix, f32x2 with split P/Q accumulators, occupancy-tuned.
// per (h,w): Yf[b,i] = sum_j K[i,j] Xf[b,j], K from S0/S1 on the fly.
// 512 threads: thread (i = tid&127, bq = tid>>7) owns 8 b's. 2 blocks/SM.
// ---------------------------------------------------------------------------
__global__ void __launch_bounds__(512, 2) mix_kernel() {
    __shared__ ulonglong2 xsm[32][64];   // 32KB: x[b][j] pairs (j even/odd)
    __shared__ float4 Ksm[4][129];       // 8.2KB: [jj2][i] = (kr0,ki0,kr1,ki1)
    int tid = threadIdx.x;
    int hw = blockIdx.x;
    int h = hw / WM, w = hw % WM;
    int i = tid & 127, bq = tid >> 7;
    const float4* A  = g_S0 + (size_t)h * CO * CI;
    const float4* Bm = g_S1 + (size_t)w * CO * CI;
    const u64* Xb = (const u64*)g_Xf + (size_t)hw * BATCH * CI;
    const float SCALE = 1.0f / 16384.0f;

    // stage all x once (u64 per (b,j)); first chunk's barrier covers this
    u64* xflat = (u64*)xsm;
    for (int t = tid; t < 32 * 128; t += 512)
        xflat[t] = Xb[(t >> 7) * CI + (t & 127)];

    // K staging ownership: one (ii, jj2) per thread per chunk
    int kjj2 = tid & 3, kii = tid >> 2;

    u64 accP[8], accQ[8];
#pragma unroll
    for (int bb = 0; bb < 8; bb++) { accP[bb] = 0; accQ[bb] = 0; }

    for (int chunk = 0; chunk < 16; chunk++) {
        __syncthreads();   // Ksm free to overwrite; x staged (chunk 0)
        {
            int e = kii * CI + chunk * 8 + 2 * kjj2;
            float4 pa0 = A[e], pa1 = A[e + 1];
            float4 pb0 = Bm[e], pb1 = Bm[e + 1];
            float kr0 = pa0.x * pb0.x - pa0.y * pb0.y + pa0.z * pb0.z - pa0.w * pb0.w;
            float ki0 = pa0.x * pb0.y + pa0.y * pb0.x + pa0.z * pb0.w + pa0.w * pb0.z;
            float kr1 = pa1.x * pb1.x - pa1.y * pb1.y + pa1.z * pb1.z - pa1.w * pb1.w;
            float ki1 = pa1.x * pb1.y + pa1.y * pb1.x + pa1.z * pb1.w + pa1.w * pb1.z;
            Ksm[kjj2][kii] = make_float4(kr0 * SCALE, ki0 * SCALE, kr1 * SCALE, ki1 * SCALE);
        }
        __syncthreads();
#pragma unroll
        for (int jj2 = 0; jj2 < 4; jj2++) {
            float4 kk = Ksm[jj2][i];
            u64 kc0 = pk2(kk.x, kk.x), ks0 = pk2(kk.y, kk.y);
            u64 kc1 = pk2(kk.z, kk.z), ks1 = pk2(kk.w, kk.w);
            int jidx = chunk * 4 + jj2;
#pragma unroll
            for (int bb = 0; bb < 8; bb++) {
                ulonglong2 xx = xsm[bq * 8 + bb][jidx];
                accP[bb] = f2fma(xx.x, kc0, accP[bb]);
                accQ[bb] = f2fma(xx.x, ks0, accQ[bb]);
                accP[bb] = f2fma(xx.y, kc1, accP[bb]);
                accQ[bb] = f2fma(xx.y, ks1, accQ[bb]);
            }
        }
    }
    float2* dst = g_Yf + (size_t)hw * BATCH * CO;
#pragma unroll
    for (int bb = 0; bb < 8; bb++) {
        float pr, pi, qr, qi;
        up2(accP[bb], pr, pi);
        up2(accQ[bb], qr, qi);
        dst[(bq * 8 + bb) * CO + i] = make_float2(pr - qi, pi + qr);
    }
}

// ---------------------------------------------------------------------------
// Inverse H: Z[b,y,w,i] = sum_h Yf[h,w,b,i] e^{+2pi i m(h) y/128}.
// ---------------------------------------------------------------------------
__global__ void __launch_bounds__(512) invH_kernel() {
    __shared__ u64 ys[32][128];
    __shared__ u64 twcc[128];
    __shared__ u64 twss[128];
    int tid = threadIdx.x;
    if (tid < 128) {
        float s, c;
        sincospif((float)tid / 64.0f, &s, &c);
        twcc[tid] = pk2(c, c);
        twss[tid] = pk2(s, s);
    }
    int hw = blockIdx.x;
    int b = hw / WM, w = hw % WM;
    int y0 = blockIdx.y * 32;
    int i = tid & 127, ysub = tid >> 7;
    int yb = y0 + ysub * 8;

    const u64* Ysrc = (const u64*)g_Yf;
    for (int t = tid; t < 32 * 128; t += 512) {
        int h = t >> 7, ii = t & 127;
        ys[h][ii] = Ysrc[((size_t)(h * WM + w) * BATCH + b) * CO + ii];
    }
    __syncthreads();

    u64 acc[8];
    {   // m = 0
        u64 v0 = ys[0][i];
#pragma unroll
        for (int k = 0; k < 8; k++) acc[k] = v0;
    }
    {   // m = -16 (h=16)
        u64 v = ys[16][i];
        float vr, vi; up2(v, vr, vi);
        u64 vs = pk2(vi, -vr);
        int idx = (16 * yb) & 127;
#pragma unroll
        for (int k = 0; k < 8; k++) {
            acc[k] = f2fma(v,  twcc[idx], acc[k]);
            acc[k] = f2fma(vs, twss[idx], acc[k]);
            idx = (idx + 16) & 127;
        }
    }
#pragma unroll 3
    for (int m = 1; m < 16; m++) {
        u64 y1 = ys[m][i];
        u64 y2 = ys[32 - m][i];
        float ar, ai, br, bi;
        up2(y1, ar, ai); up2(y2, br, bi);
        u64 s  = pk2(ar + br, ai + bi);
        u64 dp = pk2(-(ai - bi), ar - br);
        int idx = (m * yb) & 127;
#pragma unroll
        for (int k = 0; k < 8; k++) {
            acc[k] = f2fma(s,  twcc[idx], acc[k]);
            acc[k] = f2fma(dp, twss[idx], acc[k]);
            idx = (idx + m) & 127;
        }
    }
    u64* Zd = (u64*)g_Z;
#pragma unroll
    for (int k = 0; k < 8; k++) {
        int y = yb + k;
        Zd[((size_t)(b * NHH + y) * WM + w) * CO + i] = acc[k];
    }
}

// ---------------------------------------------------------------------------
// Inverse W (hermitian, real output), even/odd + pair symmetry, f32x2,
// split accumulator chains for ILP.
// ---------------------------------------------------------------------------
__global__ void __launch_bounds__(128) invW_kernel(float* __restrict__ out) {
    __shared__ u64 tw2[17][33];   // (cos(2pi w x/128), -sin(...)), x in [0,32]
    int tid = threadIdx.x;
    for (int t = tid; t < 17 * 33; t += 128) {
        int w = t / 33, x = t % 33;
        float s, c;
        sincospif((float)(w * x) / 64.0f, &s, &c);
        tw2[w][x] = pk2(c, -s);
    }
    __syncthreads();

    int b = blockIdx.x >> 7, y = blockIdx.x & 127;
    const float2* zrow = g_Z + (size_t)(b * NHH + y) * WM * CO;

    u64 zw[WM];
#pragma unroll
    for (int w = 0; w < WM; w++) {
        float2 v = zrow[w * CO + tid];
        float cw = (w == 0) ? 1.0f : 2.0f;
        zw[w] = pk2(v.x * cw, v.y * cw);
    }

    float* orow = out + (size_t)(b * NHH + y) * NWW * CO + tid;
    for (int x = 0; x <= 32; x++) {
        u64 aE0 = 0, aE1 = 0, aO0 = 0, aO1 = 0;
#pragma unroll
        for (int e = 0; e < 5; e++)
            aE0 = f2fma(zw[2 * e], tw2[2 * e][x], aE0);
#pragma unroll
        for (int e = 5; e < 9; e++)
            aE1 = f2fma(zw[2 * e], tw2[2 * e][x], aE1);
#pragma unroll
        for (int o = 0; o < 4; o++)
            aO0 = f2fma(zw[2 * o + 1], tw2[2 * o + 1][x], aO0);
#pragma unroll
        for (int o = 4; o < 8; o++)
            aO1 = f2fma(zw[2 * o + 1], tw2[2 * o + 1][x], aO1);
        u64 aE = f2add(aE0, aE1);
        u64 aO = f2add(aO0, aO1);
        float eR, eI, oR, oI;
        up2(aE, eR, eI);
        up2(aO, oR, oI);
        float a0 = eR + oR, b0 = eI + oI;   // acc(x)
        float a1 = eR - oR, b1 = eI - oI;   // acc(x+64)
        if (x == 0) {
            orow[0]            = a0 + b0;
            orow[64 * CO]      = a1 + b1;
        } else if (x == 32) {
            orow[32 * CO]      = a0 + b0;
            orow[96 * CO]      = a1 + b1;
        } else {
            orow[(size_t)x * CO]          = a0 + b0;
            orow[(size_t)(128 - x) * CO]  = a0 - b0;
            orow[(size_t)(x + 64) * CO]   = a1 + b1;
            orow[(size_t)(64 - x) * CO]   = a1 - b1;
        }
    }
}

// ---------------------------------------------------------------------------
extern "C" void kernel_launch(void* const* d_in, const int* in_sizes, int n_in,
                              void* d_out, int out_size) {
    const float*  X   = (const float*) d_in[0];
    const float2* ko0 = (const float2*)d_in[1];
    const float2* ki0 = (const float2*)d_in[2];
    const float2* ko1 = (const float2*)d_in[3];
    const float2* ki1 = (const float2*)d_in[4];
    float* out = (float*)d_out;

    s_kernel<<<dim3(HM * DEG + WM * DEG, 8), 256>>>(ko0, ki0, ko1, ki1);
    fwdW_kernel<<<BATCH * 64, 256>>>(X);
    fwdH_kernel<<<BATCH * WM, 1024>>>();
    mix_kernel<<<NHW, 512>>>();
    invH_kernel<<<dim3(BATCH * WM, 4), 512>>>();
    invW_kernel<<<BATCH * NHH, 128>>>(out);
}

// round 7
// speedup vs baseline: 2.4232x; 1.1475x over previous
#include <cuda_runtime.h>
#include <math.h>

// ---------------------------------------------------------------------------
// TensorizedSpectralConv: B=32, H=W=128, C=128, modes 32x17, deg 2, rank 64
// Round 6: mix double-buffer + L1 prefetch; fwdH/invH even-odd radix split;
// invW 256-thread blocks.
// ---------------------------------------------------------------------------

#define BATCH 32
#define NHH   128
#define NWW   128
#define CI    128
#define CO    128
#define WM    17
#define HM    32
#define DEG   2
#define RANK  64
#define NHW   (HM*WM)   // 544

typedef unsigned long long u64;

__device__ u64    g_X1[BATCH*WM*NHH*CI];     // 71.3 MB  [b][w][y][c] (re,im)
__device__ float4 g_S0[HM*CO*CI];            //  8.4 MB  (d0.re,d0.im,d1.re,d1.im)
__device__ float4 g_S1[WM*CO*CI];            //  4.5 MB
__device__ float2 g_Xf[NHW*BATCH*CI];        // 17.8 MB  [h][w][b][c]
__device__ float2 g_Yf[NHW*BATCH*CO];        // 17.8 MB  [h][w][b][i]
__device__ float2 g_Z [BATCH*NHH*WM*CO];     // 71.3 MB  [b][y][w][i]

__device__ __forceinline__ u64 pk2(float x, float y) {
    u64 r; asm("mov.b64 %0,{%1,%2};" : "=l"(r) : "f"(x), "f"(y)); return r;
}
__device__ __forceinline__ void up2(u64 v, float& x, float& y) {
    asm("mov.b64 {%0,%1},%2;" : "=f"(x), "=f"(y) : "l"(v));
}
__device__ __forceinline__ u64 f2fma(u64 a, u64 b, u64 c) {
    u64 d; asm("fma.rn.f32x2 %0,%1,%2,%3;" : "=l"(d) : "l"(a), "l"(b), "l"(c)); return d;
}
__device__ __forceinline__ u64 f2add(u64 a, u64 b) {
    u64 d; asm("add.rn.f32x2 %0,%1,%2;" : "=l"(d) : "l"(a), "l"(b)); return d;
}
__device__ __forceinline__ void pf_l1(const void* p) {
    asm volatile("prefetch.global.L1 [%0];" :: "l"(p));
}

__device__ __forceinline__ float2 cfma(float2 a, float2 b, float2 acc) {
    acc.x = fmaf(a.x, b.x, acc.x);
    acc.x = fmaf(-a.y, b.y, acc.x);
    acc.y = fmaf(a.x, b.y, acc.y);
    acc.y = fmaf(a.y, b.x, acc.y);
    return acc;
}

// ---------------------------------------------------------------------------
// S build (both axes in one launch): block per (axis, mode, d, i-chunk-of-16).
// ---------------------------------------------------------------------------
__global__ void __launch_bounds__(256) s_kernel(const float2* __restrict__ ko0,
                                                const float2* __restrict__ ki0,
                                                const float2* __restrict__ ko1,
                                                const float2* __restrict__ ki1) {
    int which = (blockIdx.x >= HM * DEG);
    int hd = which ? (blockIdx.x - HM * DEG) : blockIdx.x;
    const float2* ko = which ? ko1 : ko0;
    const float2* ki = which ? ki1 : ki0;
    float4* S = which ? g_S1 : g_S0;
    int h  = hd >> 1;
    int d  = hd & 1;
    int i0 = blockIdx.y * 16;
    __shared__ float2 kis[128][33];
    __shared__ float2 kos[16][33];
    int tid = threadIdx.x;
    int j = tid & 127, ih = tid >> 7;

    float2 acc[8];
#pragma unroll
    for (int ii = 0; ii < 8; ii++) acc[ii] = make_float2(0.f, 0.f);

    for (int r0 = 0; r0 < RANK; r0 += 32) {
        __syncthreads();
        for (int t = tid; t < 128 * 32; t += 256) {
            int jj = t >> 5, r = t & 31;
            kis[jj][r] = ki[((h * CI + jj) * DEG + d) * RANK + r0 + r];
        }
        for (int t = tid; t < 16 * 32; t += 256) {
            int ii = t >> 5, r = t & 31;
            kos[ii][r] = ko[((h * CO + i0 + ii) * DEG + d) * RANK + r0 + r];
        }
        __syncthreads();
        for (int r = 0; r < 32; r++) {
            float2 bj = kis[j][r];
#pragma unroll
            for (int ii = 0; ii < 8; ii++)
                acc[ii] = cfma(kos[ih * 8 + ii][r], bj, acc[ii]);
        }
    }
#pragma unroll
    for (int ii = 0; ii < 8; ii++) {
        int i = i0 + ih * 8 + ii;
        ((float2*)&S[(size_t)(h * CO + i) * CI + j])[d] = acc[ii];
    }
}

// ---------------------------------------------------------------------------
// Forward W DFT (real input, 17 modes). Even/odd split + pair fold, f32x2.
// ---------------------------------------------------------------------------
__global__ void __launch_bounds__(256) fwdW_kernel(const float* __restrict__ X) {
    __shared__ u64 tw2[17][33];   // (cos(2pi w u/128), -sin(...)), u in [0,32]
    int tid = threadIdx.x;
    for (int t = tid; t < 17 * 33; t += 256) {
        int w = t / 33, u = t % 33;
        float s, c;
        sincospif((float)(w * u) / 64.0f, &s, &c);
        tw2[w][u] = pk2(c, -s);
    }
    __syncthreads();

    int c = tid & 127, ys = tid >> 7;
    int b = blockIdx.x >> 6;
    int y = ((blockIdx.x & 63) << 1) | ys;
    const float* base = X + ((size_t)(b * NHH + y) * NWW) * CI + c;

    float v0  = base[0],       v32 = base[32 * CI];
    float v64 = base[64 * CI], v96 = base[96 * CI];
    float pE0  = v0 + v64,  pO0  = v0 - v64;
    float pE32 = v32 + v96, pO32 = v32 - v96;

    u64 accE[9], accO[8];
#pragma unroll
    for (int e = 0; e < 9; e++)
        accE[e] = pk2(pE0 + ((e & 1) ? -pE32 : pE32), 0.f);
#pragma unroll
    for (int o = 0; o < 8; o++)
        accO[o] = pk2(pO0, (o & 1) ? pO32 : -pO32);

    for (int u = 1; u < 32; u++) {
        float va = base[u * CI];
        float vb = base[(u + 64) * CI];
        float vc = base[(64 - u) * CI];
        float vd = base[(128 - u) * CI];
        float pEu = va + vb, pOu = va - vb;
        float pEv = vc + vd, pOv = vc - vd;
        u64 sdE = pk2(pEu + pEv, pEu - pEv);
        u64 dsO = pk2(pOu - pOv, pOu + pOv);
#pragma unroll
        for (int e = 0; e < 9; e++)
            accE[e] = f2fma(sdE, tw2[2 * e][u], accE[e]);
#pragma unroll
        for (int o = 0; o < 8; o++)
            accO[o] = f2fma(dsO, tw2[2 * o + 1][u], accO[o]);
    }

    u64* dst = g_X1 + ((size_t)b * WM * NHH + y) * CI + c;
#pragma unroll
    for (int w = 0; w < WM; w++)
        dst[(size_t)w * NHH * CI] = (w & 1) ? accO[w >> 1] : accE[w >> 1];
}

// ---------------------------------------------------------------------------
// Forward H DFT (32 kept modes), even/odd split over y+64 (mode parity = h&1)
// + pair fold over 64-y, f32x2. Block per (b,w); 1024 threads = 32 h x 32 lanes.
// even m: contrib = sE*cos - i dE*sin;  odd m: contrib = dO*cos - i sO*sin.
// ---------------------------------------------------------------------------
__global__ void __launch_bounds__(1024) fwdH_kernel() {
    __shared__ u64 stg[4][16][128];   // 64KB: [sE, dEm, dO, sOm]
    __shared__ u64 twcc[128], twss[128];
    int tid = threadIdx.x;
    if (tid < 128) {
        float s, c;
        sincospif((float)tid / 64.0f, &s, &c);
        twcc[tid] = pk2(c, c);
        twss[tid] = pk2(s, s);
    }
    int b = blockIdx.x / WM, w = blockIdx.x % WM;
    int lane = tid & 31, h = tid >> 5;
    int m = (h < 16) ? h : (96 + h);
    int p = h & 1;
    float sg = ((h >> 1) & 1) ? -1.f : 1.f;
    const u64* src = g_X1 + ((size_t)b * WM + w) * NHH * CI;

    // specials: y = 0, 32 (and +64 folded)
    u64 acc[4];
#pragma unroll
    for (int q = 0; q < 4; q++) {
        int c = lane + 32 * q;
        float r0, i0, r32, i32, r64, i64, r96, i96;
        up2(src[c], r0, i0);
        up2(src[32 * CI + c], r32, i32);
        up2(src[64 * CI + c], r64, i64);
        up2(src[96 * CI + c], r96, i96);
        if (p == 0) {
            // pE0 + sg*pE32
            acc[q] = pk2(fmaf(sg, r32 + r96, r0 + r64),
                         fmaf(sg, i32 + i96, i0 + i64));
        } else {
            // pO0 + sg*(-i)*pO32 = (pO0.re + sg*pO32.im, pO0.im - sg*pO32.re)
            acc[q] = pk2(fmaf(sg, i32 - i96, r0 - r64),
                         fmaf(-sg, r32 - r96, i0 - i64));
        }
    }

    const u64* sPtr = p ? &stg[2][0][0] : &stg[0][0][0];
    const u64* mPtr = p ? &stg[3][0][0] : &stg[1][0][0];

    for (int chunk = 0; chunk < 2; chunk++) {
        int ylo = 1 + 16 * chunk;
        int cnt = chunk ? 15 : 16;
        __syncthreads();
        for (int t = tid; t < cnt * 128; t += 1024) {
            int yy = t >> 7, cc = t & 127;
            int yp = ylo + yy;
            float ar, ai, br, bi, cr, ci2, dr, di;
            up2(src[(size_t)yp * CI + cc], ar, ai);
            up2(src[(size_t)(yp + 64) * CI + cc], br, bi);
            up2(src[(size_t)(64 - yp) * CI + cc], cr, ci2);
            up2(src[(size_t)(128 - yp) * CI + cc], dr, di);
            float pEyr = ar + br, pEyi = ai + bi;
            float pOyr = ar - br, pOyi = ai - bi;
            float pEvr = cr + dr, pEvi = ci2 + di;
            float pOvr = cr - dr, pOvi = ci2 - di;
            stg[0][yy][cc] = pk2(pEyr + pEvr, pEyi + pEvi);              // sE
            stg[1][yy][cc] = pk2(pEyi - pEvi, -(pEyr - pEvr));           // -i*dE
            stg[2][yy][cc] = pk2(pOyr - pOvr, pOyi - pOvi);              // dO
            stg[3][yy][cc] = pk2(pOyi + pOvi, -(pOyr + pOvr));           // -i*sO
        }
        __syncthreads();
#pragma unroll 4
        for (int yy = 0; yy < cnt; yy++) {
            int idx = (m * (ylo + yy)) & 127;
            u64 cc = twcc[idx], ss = twss[idx];
#pragma unroll
            for (int q = 0; q < 4; q++) {
                int c = lane + 32 * q;
                acc[q] = f2fma(sPtr[yy * 128 + c], cc, acc[q]);
                acc[q] = f2fma(mPtr[yy * 128 + c], ss, acc[q]);
            }
        }
    }
    u64* dst = (u64*)g_Xf + ((size_t)(h * WM + w) * BATCH + b) * CI;
#pragma unroll
    for (int q = 0; q < 4; q++) dst[lane + 32 * q] = acc[q];
}

// ---------------------------------------------------------------------------
// Mode mix, f32x2 P/Q accumulators, double-buffered K staging (1 barrier per
// chunk) + L1 prefetch of next chunk's A/B lines during the FMA phase.
// ---------------------------------------------------------------------------
__global__ void __launch_bounds__(512, 2) mix_kernel() {
    __shared__ ulonglong2 xsm[32][64];    // 32KB: x[b][j] pairs (j even/odd)
    __shared__ float4 Ksm[2][4][129];     // 16.5KB double-buffered
    int tid = threadIdx.x;
    int hw = blockIdx.x;
    int h = hw / WM, w = hw % WM;
    int i = tid & 127, bq = tid >> 7;
    const float4* A  = g_S0 + (size_t)h * CO * CI;
    const float4* Bm = g_S1 + (size_t)w * CO * CI;
    const u64* Xb = (const u64*)g_Xf + (size_t)hw * BATCH * CI;
    const float SCALE = 1.0f / 16384.0f;

    // stage all x once; barrier of chunk 0 covers visibility
    u64* xflat = (u64*)xsm;
    for (int t = tid; t < 32 * 128; t += 512)
        xflat[t] = Xb[(t >> 7) * CI + (t & 127)];

    int kjj2 = tid & 3, kii = tid >> 2;
    int ebase = kii * CI + 2 * kjj2;
    pf_l1(&A[ebase]);
    pf_l1(&Bm[ebase]);

    u64 accP[8], accQ[8];
#pragma unroll
    for (int bb = 0; bb < 8; bb++) { accP[bb] = 0; accQ[bb] = 0; }

    for (int chunk = 0; chunk < 16; chunk++) {
        int buf = chunk & 1;
        {
            int e = ebase + chunk * 8;
            float4 pa0 = A[e], pa1 = A[e + 1];
            float4 pb0 = Bm[e], pb1 = Bm[e + 1];
            float kr0 = pa0.x * pb0.x - pa0.y * pb0.y + pa0.z * pb0.z - pa0.w * pb0.w;
            float ki0 = pa0.x * pb0.y + pa0.y * pb0.x + pa0.z * pb0.w + pa0.w * pb0.z;
            float kr1 = pa1.x * pb1.x - pa1.y * pb1.y + pa1.z * pb1.z - pa1.w * pb1.w;
            float ki1 = pa1.x * pb1.y + pa1.y * pb1.x + pa1.z * pb1.w + pa1.w * pb1.z;
            Ksm[buf][kjj2][kii] = make_float4(kr0 * SCALE, ki0 * SCALE,
                                              kr1 * SCALE, ki1 * SCALE);
        }
        if (chunk < 15) {
            pf_l1(&A[ebase + (chunk + 1) * 8]);
            pf_l1(&Bm[ebase + (chunk + 1) * 8]);
        }
        __syncthreads();
#pragma unroll
        for (int jj2 = 0; jj2 < 4; jj2++) {
            float4 kk = Ksm[buf][jj2][i];
            u64 kc0 = pk2(kk.x, kk.x), ks0 = pk2(kk.y, kk.y);
            u64 kc1 = pk2(kk.z, kk.z), ks1 = pk2(kk.w, kk.w);
            int jidx = chunk * 4 + jj2;
#pragma unroll
            for (int bb = 0; bb < 8; bb++) {
                ulonglong2 xx = xsm[bq * 8 + bb][jidx];
                accP[bb] = f2fma(xx.x, kc0, accP[bb]);
                accQ[bb] = f2fma(xx.x, ks0, accQ[bb]);
                accP[bb] = f2fma(xx.y, kc1, accP[bb]);
                accQ[bb] = f2fma(xx.y, ks1, accQ[bb]);
            }
        }
    }
    float2* dst = g_Yf + (size_t)hw * BATCH * CO;
#pragma unroll
    for (int bb = 0; bb < 8; bb++) {
        float pr, pi, qr, qi;
        up2(accP[bb], pr, pi);
        up2(accQ[bb], qr, qi);
        dst[(bq * 8 + bb) * CO + i] = make_float2(pr - qi, pi + qr);
    }
}

// ---------------------------------------------------------------------------
// Inverse H with even/odd output split: accE/accO over mode parity give
// Z(y) = accE+accO and Z(y+64) = accE-accO for y in [0,64).
// Grid (b*17+w, 2); 512 thr = (i, 4 ysub), 8 y each -> 16 outputs.
// ---------------------------------------------------------------------------
__global__ void __launch_bounds__(512) invH_kernel() {
    __shared__ u64 ys[32][128];
    __shared__ u64 twcc[128];
    __shared__ u64 twss[128];
    int tid = threadIdx.x;
    if (tid < 128) {
        float s, c;
        sincospif((float)tid / 64.0f, &s, &c);
        twcc[tid] = pk2(c, c);
        twss[tid] = pk2(s, s);
    }
    int hw = blockIdx.x;
    int b = hw / WM, w = hw % WM;
    int i = tid & 127, ysub = tid >> 7;
    int yb = blockIdx.y * 32 + ysub * 8;   // y in [0,64)

    const u64* Ysrc = (const u64*)g_Yf;
    for (int t = tid; t < 32 * 128; t += 512) {
        int h = t >> 7, ii = t & 127;
        ys[h][ii] = Ysrc[((size_t)(h * WM + w) * BATCH + b) * CO + ii];
    }
    __syncthreads();

    u64 accE[8], accO[8];
    {   // m = 0 (even)
        u64 v0 = ys[0][i];
#pragma unroll
        for (int k = 0; k < 8; k++) { accE[k] = v0; accO[k] = 0; }
    }
    {   // m = -16 (h=16, even): v*e^{-i 2pi 16 y/128}
        u64 v = ys[16][i];
        float vr, vi; up2(v, vr, vi);
        u64 vs = pk2(vi, -vr);
        int idx = (16 * yb) & 127;
#pragma unroll
        for (int k = 0; k < 8; k++) {
            accE[k] = f2fma(v,  twcc[idx], accE[k]);
            accE[k] = f2fma(vs, twss[idx], accE[k]);
            idx = (idx + 16) & 127;
        }
    }
    // even pairs m = 2,4,...,14
#pragma unroll 2
    for (int m = 2; m < 16; m += 2) {
        u64 y1 = ys[m][i], y2 = ys[32 - m][i];
        float ar, ai, br, bi;
        up2(y1, ar, ai); up2(y2, br, bi);
        u64 s  = pk2(ar + br, ai + bi);
        u64 dp = pk2(-(ai - bi), ar - br);
        int idx = (m * yb) & 127;
#pragma unroll
        for (int k = 0; k < 8; k++) {
            accE[k] = f2fma(s,  twcc[idx], accE[k]);
            accE[k] = f2fma(dp, twss[idx], accE[k]);
            idx = (idx + m) & 127;
        }
    }
    // odd pairs m = 1,3,...,15
#pragma unroll 2
    for (int m = 1; m < 16; m += 2) {
        u64 y1 = ys[m][i], y2 = ys[32 - m][i];
        float ar, ai, br, bi;
        up2(y1, ar, ai); up2(y2, br, bi);
        u64 s  = pk2(ar + br, ai + bi);
        u64 dp = pk2(-(ai - bi), ar - br);
        int idx = (m * yb) & 127;
#pragma unroll
        for (int k = 0; k < 8; k++) {
            accO[k] = f2fma(s,  twcc[idx], accO[k]);
            accO[k] = f2fma(dp, twss[idx], accO[k]);
            idx = (idx + m) & 127;
        }
    }
    u64* Zd = (u64*)g_Z;
    const u64 NEG1 = pk2(-1.f, -1.f);
#pragma unroll
    for (int k = 0; k < 8; k++) {
        int y = yb + k;
        Zd[((size_t)(b * NHH + y) * WM + w) * CO + i] = f2add(accE[k], accO[k]);
        Zd[((size_t)(b * NHH + y + 64) * WM + w) * CO + i] = f2fma(accO[k], NEG1, accE[k]);
    }
}

// ---------------------------------------------------------------------------
// Inverse W (hermitian, real output), even/odd + pair symmetry, f32x2,
// split accumulator chains. 256 threads = 2 y rows.
// ---------------------------------------------------------------------------
__global__ void __launch_bounds__(256) invW_kernel(float* __restrict__ out) {
    __shared__ u64 tw2[17][33];   // (cos(2pi w x/128), -sin(...)), x in [0,32]
    int tid = threadIdx.x;
    for (int t = tid; t < 17 * 33; t += 256) {
        int w = t / 33, x = t % 33;
        float s, c;
        sincospif((float)(w * x) / 64.0f, &s, &c);
        tw2[w][x] = pk2(c, -s);
    }
    __syncthreads();

    int c = tid & 127, ysp = tid >> 7;
    int b = blockIdx.x >> 6;
    int y = ((blockIdx.x & 63) << 1) | ysp;
    const float2* zrow = g_Z + (size_t)(b * NHH + y) * WM * CO;

    u64 zw[WM];
#pragma unroll
    for (int w = 0; w < WM; w++) {
        float2 v = zrow[w * CO + c];
        float cw = (w == 0) ? 1.0f : 2.0f;
        zw[w] = pk2(v.x * cw, v.y * cw);
    }

    float* orow = out + (size_t)(b * NHH + y) * NWW * CO + c;
    for (int x = 0; x <= 32; x++) {
        u64 aE0 = 0, aE1 = 0, aO0 = 0, aO1 = 0;
#pragma unroll
        for (int e = 0; e < 5; e++)
            aE0 = f2fma(zw[2 * e], tw2[2 * e][x], aE0);
#pragma unroll
        for (int e = 5; e < 9; e++)
            aE1 = f2fma(zw[2 * e], tw2[2 * e][x], aE1);
#pragma unroll
        for (int o = 0; o < 4; o++)
            aO0 = f2fma(zw[2 * o + 1], tw2[2 * o + 1][x], aO0);
#pragma unroll
        for (int o = 4; o < 8; o++)
            aO1 = f2fma(zw[2 * o + 1], tw2[2 * o + 1][x], aO1);
        u64 aE = f2add(aE0, aE1);
        u64 aO = f2add(aO0, aO1);
        float eR, eI, oR, oI;
        up2(aE, eR, eI);
        up2(aO, oR, oI);
        float a0 = eR + oR, b0 = eI + oI;   // acc(x)
        float a1 = eR - oR, b1 = eI - oI;   // acc(x+64)
        if (x == 0) {
            orow[0]            = a0 + b0;
            orow[64 * CO]      = a1 + b1;
        } else if (x == 32) {
            orow[32 * CO]      = a0 + b0;
            orow[96 * CO]      = a1 + b1;
        } else {
            orow[(size_t)x * CO]          = a0 + b0;
            orow[(size_t)(128 - x) * CO]  = a0 - b0;
            orow[(size_t)(x + 64) * CO]   = a1 + b1;
            orow[(size_t)(64 - x) * CO]   = a1 - b1;
        }
    }
}

// ---------------------------------------------------------------------------
extern "C" void kernel_launch(void* const* d_in, const int* in_sizes, int n_in,
                              void* d_out, int out_size) {
    const float*  X   = (const float*) d_in[0];
    const float2* ko0 = (const float2*)d_in[1];
    const float2* ki0 = (const float2*)d_in[2];
    const float2* ko1 = (const float2*)d_in[3];
    const float2* ki1 = (const float2*)d_in[4];
    float* out = (float*)d_out;

    s_kernel<<<dim3(HM * DEG + WM * DEG, 8), 256>>>(ko0, ki0, ko1, ki1);
    fwdW_kernel<<<BATCH * 64, 256>>>(X);
    fwdH_kernel<<<BATCH * WM, 1024>>>();
    mix_kernel<<<NHW, 512>>>();
    invH_kernel<<<dim3(BATCH * WM, 2), 512>>>();
    invW_kernel<<<BATCH * 64, 256>>>(out);
}